// round 8
// baseline (speedup 1.0000x reference)
#include <cuda_runtime.h>
#include <cuda_fp16.h>
#include <math.h>
#include <stdint.h>

#define Bq 2
#define Lq 1536
#define Dq 1024
#define Hq 8
#define Cq 2048
#define DPHq 256
#define Mq (Bq*Lq)   /* 3072 */

typedef __half fp16;

// ---------------- scratch (static device globals; no allocation) ----------------
__device__ __align__(128) fp16  d_xlnh[(size_t)Mq*Dq],  d_xlnl[(size_t)Mq*Dq];
__device__ __align__(128) float d_y[(size_t)Mq*4096];
__device__ __align__(128) fp16  d_x1h[(size_t)Mq*Cq],  d_x1l[(size_t)Mq*Cq];
__device__ __align__(128) float d_qk[(size_t)Mq*Cq];
__device__ __align__(128) fp16  d_qkh[(size_t)Mq*Cq],  d_qkl[(size_t)Mq*Cq];
__device__ __align__(128) float d_proj[(size_t)Mq*4096];
__device__ __align__(128) fp16  d_pjh[(size_t)Mq*4096], d_pjl[(size_t)Mq*4096];
__device__ __align__(128) float d_v[(size_t)Mq*Cq];
__device__ __align__(128) fp16  d_vbh[(size_t)Mq*Cq],  d_vbl[(size_t)Mq*Cq];
__device__ __align__(128) fp16  d_xmh[(size_t)Mq*Cq],  d_xml[(size_t)Mq*Cq];
__device__ float d_gates[(size_t)Mq*16];
__device__ float d_g[16*Lq];
__device__ float d_M[16*Lq];
__device__ float d_enm[16*Lq];
__device__ __align__(128) fp16  d_w1f[4096*1024];
__device__ __align__(128) fp16  d_cwtf[(size_t)4*Cq*Cq];
__device__ __align__(128) fp16  d_wqkTf[Hq*512*256];
__device__ __align__(128) fp16  d_wvTf[Hq*256*256];
__device__ __align__(128) fp16  d_w2f[1024*2048];

// ---------------- helpers ----------------
__device__ __forceinline__ uint32_t smem_u32(const void* p){
    return (uint32_t)__cvta_generic_to_shared(p);
}
__device__ __forceinline__ void cp16(uint32_t dst, const void* src){
    asm volatile("cp.async.cg.shared.global [%0], [%1], 16;" :: "r"(dst), "l"(src));
}
__device__ __forceinline__ void cp_commit(){ asm volatile("cp.async.commit_group;" ::: "memory"); }
__device__ __forceinline__ void cp_wait0(){ asm volatile("cp.async.wait_group 0;" ::: "memory"); }
__device__ __forceinline__ void cp_wait1(){ asm volatile("cp.async.wait_group 1;" ::: "memory"); }
__device__ __forceinline__ void cp_wait2(){ asm volatile("cp.async.wait_group 2;" ::: "memory"); }

__device__ __forceinline__ void ldsm_x4(uint32_t* r, uint32_t addr){
    asm volatile("ldmatrix.sync.aligned.m8n8.x4.shared.b16 {%0,%1,%2,%3}, [%4];"
                 : "=r"(r[0]), "=r"(r[1]), "=r"(r[2]), "=r"(r[3]) : "r"(addr));
}
__device__ __forceinline__ void ldsm_x4t(uint32_t* r, uint32_t addr){
    asm volatile("ldmatrix.sync.aligned.m8n8.x4.trans.shared.b16 {%0,%1,%2,%3}, [%4];"
                 : "=r"(r[0]), "=r"(r[1]), "=r"(r[2]), "=r"(r[3]) : "r"(addr));
}
__device__ __forceinline__ void mma16816(float* d, const uint32_t* a, const uint32_t* b){
    asm volatile(
        "mma.sync.aligned.m16n8k16.row.col.f32.f16.f16.f32 "
        "{%0,%1,%2,%3}, {%4,%5,%6,%7}, {%8,%9}, {%0,%1,%2,%3};"
        : "+f"(d[0]), "+f"(d[1]), "+f"(d[2]), "+f"(d[3])
        : "r"(a[0]), "r"(a[1]), "r"(a[2]), "r"(a[3]), "r"(b[0]), "r"(b[1]));
}
__device__ __forceinline__ void split_h(float v, fp16& hi, fp16& lo){
    hi = __float2half_rn(v);
    lo = __float2half_rn(v - __half2float(hi));
}
__device__ __forceinline__ uint32_t pack2(fp16 a, fp16 b){
    uint16_t ua = *(uint16_t*)&a, ub = *(uint16_t*)&b;
    return (uint32_t)ua | ((uint32_t)ub << 16);
}

// ---------------- prep kernels ----------------
__global__ void quant_plain(const float* __restrict__ w, fp16* __restrict__ f, long n){
    long i = (long)blockIdx.x*256 + threadIdx.x;
    if (i >= n) return;
    f[i] = __float2half_rn(w[i]);
}
__global__ void prep_cwt(const float* __restrict__ cw, fp16* __restrict__ f){
    long idx = (long)blockIdx.x*256 + threadIdx.x;
    if (idx >= (long)4*Cq*Cq) return;
    int k  = (int)(idx >> 22);
    long rem = idx & ((1L<<22)-1);
    int co = (int)(rem >> 11), ci = (int)(rem & 2047);
    f[idx] = __float2half_rn(cw[(((long)co<<11) + ci)*4 + k]);
}
__global__ void prep_wqkv(const float* __restrict__ wqk, const float* __restrict__ wv,
                          fp16* __restrict__ qf, fp16* __restrict__ vf){
    int idx = blockIdx.x*256 + threadIdx.x;
    if (idx < Hq*512*256){
        int hh = idx/(512*256); int r = idx%(512*256); int o = r/256; int i = r%256;
        qf[idx] = __float2half_rn(wqk[hh*131072 + i*512 + o]);
    } else {
        int j = idx - Hq*512*256;
        if (j < Hq*256*256){
            int hh = j/65536; int r = j%65536; int o = r/256; int i = r%256;
            vf[j] = __float2half_rn(wv[hh*65536 + i*256 + o]);
        }
    }
}

// ---------------- LayerNorm on x -> fp16 hi/lo ----------------
__global__ __launch_bounds__(256) void ln_kernel(const float* __restrict__ x,
        const float* __restrict__ w, const float* __restrict__ bb,
        fp16* __restrict__ oh, fp16* __restrict__ ol){
    int m = blockIdx.x, t = threadIdx.x;
    __shared__ float s1[256], s2[256];
    float v[4]; float s = 0.f, q = 0.f;
    #pragma unroll
    for (int u=0;u<4;u++){ v[u] = x[(long)m*Dq + t + u*256]; s += v[u]; q += v[u]*v[u]; }
    s1[t] = s; s2[t] = q; __syncthreads();
    for (int off=128; off; off>>=1){
        if (t < off){ s1[t] += s1[t+off]; s2[t] += s2[t+off]; }
        __syncthreads();
    }
    float mu = s1[0]*(1.f/1024.f);
    float var = s2[0]*(1.f/1024.f) - mu*mu;
    float rs = rsqrtf(var + 1e-5f);
    #pragma unroll
    for (int u=0;u<4;u++){
        int c = t + u*256;
        float val = (v[u]-mu)*rs*w[c] + bb[c];
        fp16 hi, lo; split_h(val, hi, lo);
        oh[(long)m*Dq + c] = hi; ol[(long)m*Dq + c] = lo;
    }
}

// ---------------- fp16x2 mma.sync GEMM (512 threads): C = A @ B^T ----------------
// A split hi/lo fp16 (2 products), B single fp16.
// 4x4 warp grid, warp tile (MT*16) x 32; BM = MT*64.
// epi bits: 1=bias, 2=silu, 4=residual add, 8=conv mode (batch-dependent taps)
struct G5P {
    const fp16 *Ah, *Al, *Bf;
    float* Cf;
    fp16 *Oh, *Ol;
    const float* bias; const float* add;
    int K, lda, ldb, ldc, ldo, ldadd, epi, ntaps, ntaps2, splitNmax;
    long aZ, bZ, cZ, biasZ, oZ;
    long aTap[2], bTap[2];
    long aTap2[2], bTap2[2];
};

template<int MT>
__global__ __launch_bounds__(512, 1) void hgemm(G5P p){
    constexpr int BM = MT*64;
    constexpr int TA = BM*80;
    constexpr int TB = 10240;
    constexpr int STG = 2*TA + TB;
    extern __shared__ char sm[];
    int tid = threadIdx.x;
    int warp = tid >> 5, lane = tid & 31;
    int wm = warp >> 2, wn = warp & 3;     // 4 x 4 warp grid

    long m0 = (long)blockIdx.y*BM;
    int  n0 = blockIdx.x*128;

    long arow; int ntaps; long aT[2], bT[2];
    if (p.epi & 8){
        int batch = (int)(m0 / Lq);
        arow = m0 - (long)batch*Lq;
        if (batch == 0){ ntaps = p.ntaps;  aT[0]=p.aTap[0];  bT[0]=p.bTap[0];  aT[1]=p.aTap[1];  bT[1]=p.bTap[1]; }
        else           { ntaps = p.ntaps2; aT[0]=p.aTap2[0]; bT[0]=p.bTap2[0]; aT[1]=p.aTap2[1]; bT[1]=p.bTap2[1]; }
    } else {
        arow = m0; ntaps = p.ntaps;
        aT[0]=p.aTap[0]; bT[0]=p.bTap[0]; aT[1]=p.aTap[1]; bT[1]=p.bTap[1];
    }

    long aoff = (long)blockIdx.z*p.aZ + arow*p.lda;
    long boff = (long)blockIdx.z*p.bZ + (long)n0*p.ldb;
    int cpt = p.K >> 5;
    int nch = ntaps * cpt;

    uint32_t smb = smem_u32(sm);
    float acc[MT][4][4] = {};

    auto loadChunk = [&](int c){
        int tap = c / cpt;
        int k0  = (c - tap*cpt) << 5;
        uint32_t stg = smb + (c % 3)*STG;
        const fp16* aB[2] = { p.Ah + aoff + aT[tap] + k0, p.Al + aoff + aT[tap] + k0 };
        #pragma unroll
        for (int t=0; t<2; t++){
            const fp16* base = aB[t];
            #pragma unroll
            for (int j = tid; j < BM*4; j += 512){
                int row = j >> 2, ch = j & 3;
                cp16(stg + t*TA + row*80 + ch*16, base + (long)row*p.lda + ch*8);
            }
        }
        const fp16* base = p.Bf + boff + bT[tap] + k0;
        #pragma unroll
        for (int j = tid; j < 512; j += 512){
            int row = j >> 2, ch = j & 3;
            cp16(stg + 2*TA + row*80 + ch*16, base + (long)row*p.ldb + ch*8);
        }
    };

    loadChunk(0); cp_commit();
    if (nch > 1){ loadChunk(1); cp_commit(); }

    for (int c=0; c<nch; c++){
        if (c+2 < nch){ loadChunk(c+2); cp_commit(); cp_wait2(); }
        else if (c+1 < nch){ cp_wait1(); }
        else { cp_wait0(); }
        __syncthreads();

        uint32_t stg = smb + (c % 3)*STG;
        uint32_t aH = stg, aL = stg + TA, bB = stg + 2*TA;

        int lr = lane & 15, lcs = lane >> 4;
        int gb = lane >> 3, bnr = lane & 7;
        int rowA = wm*(MT*16) + lr;
        int rowB = wn*32 + ((gb >> 1) << 3) + bnr;

        #pragma unroll
        for (int ks=0; ks<2; ks++){
            uint32_t ahf[MT][4], alf[MT][4], bf[4][2];
            uint32_t aoffb = (uint32_t)((rowA*5 + ks*2 + lcs) * 16);
            #pragma unroll
            for (int mt=0; mt<MT; mt++){
                ldsm_x4(ahf[mt], aH + aoffb + mt*1280);
                ldsm_x4(alf[mt], aL + aoffb + mt*1280);
            }
            uint32_t boffb = (uint32_t)((rowB*5 + ks*2 + (gb & 1)) * 16);
            uint32_t t4[4];
            #pragma unroll
            for (int np=0; np<2; np++){
                ldsm_x4(t4, bB + boffb + np*1280);
                bf[np*2][0]=t4[0]; bf[np*2][1]=t4[1]; bf[np*2+1][0]=t4[2]; bf[np*2+1][1]=t4[3];
            }
            // product-major ordering: hi term across all tiles, then lo term
            #pragma unroll
            for (int mt=0; mt<MT; mt++)
                #pragma unroll
                for (int nt=0; nt<4; nt++)
                    mma16816(acc[mt][nt], ahf[mt], bf[nt]);
            #pragma unroll
            for (int mt=0; mt<MT; mt++)
                #pragma unroll
                for (int nt=0; nt<4; nt++)
                    mma16816(acc[mt][nt], alf[mt], bf[nt]);
        }
        __syncthreads();
    }

    float* eps = (float*)sm;
    #pragma unroll
    for (int mt=0; mt<MT; mt++){
        int r0 = wm*(MT*16) + mt*16 + (lane >> 2);
        #pragma unroll
        for (int nt=0; nt<4; nt++){
            int c0 = wn*32 + nt*8 + (lane & 3)*2;
            eps[r0*132 + c0]       = acc[mt][nt][0];
            eps[r0*132 + c0 + 1]   = acc[mt][nt][1];
            eps[(r0+8)*132 + c0]   = acc[mt][nt][2];
            eps[(r0+8)*132 + c0+1] = acc[mt][nt][3];
        }
    }
    __syncthreads();

    const float* bias = p.bias ? (p.bias + (long)blockIdx.z*p.biasZ) : (const float*)0;
    long czo = (long)blockIdx.z * p.cZ;
    long ozo = (long)blockIdx.z * p.oZ;
    for (int j = tid; j < BM*128; j += 512){
        int rr = j >> 7, cc = j & 127;
        long m = m0 + rr;
        int n = n0 + cc;
        float val = eps[rr*132 + cc];
        if (bias) val += bias[n];
        if (p.epi & 2){ val = val / (1.f + expf(-val)); }
        if (p.epi & 4){ val += p.add[m*p.ldadd + n]; }
        if (p.Cf) p.Cf[m*p.ldc + czo + n] = val;
        if (n < p.splitNmax){
            fp16 hi, lo; split_h(val, hi, lo);
            p.Oh[m*p.ldo + ozo + n] = hi;
            p.Ol[m*p.ldo + ozo + n] = lo;
        }
    }
}

// ---------------- gates ----------------
__global__ __launch_bounds__(256) void gates_kernel(const float* __restrict__ proj,
        const float* __restrict__ vb, const float* __restrict__ wif,
        const float* __restrict__ bif, float* __restrict__ gates){
    __shared__ float As[16*128];
    __shared__ float Ws[128*17];
    int m0 = blockIdx.x*16;
    int tid = threadIdx.x;
    int r = tid >> 4, g = tid & 15;
    float acc = 0.f;
    for (int j0=0; j0<6144; j0+=128){
        __syncthreads();
        for (int e=tid; e<2048; e+=256){
            int jj = e & 127, rr = e >> 7;
            int j = j0 + jj;
            int hh = j/768, t = j - hh*768;
            long m = m0 + rr;
            float v = (t < 512) ? proj[m*4096 + hh*512 + t]
                                : vb[m*2048 + hh*256 + (t-512)];
            As[rr*128 + jj] = v;
        }
        for (int e=tid; e<2048; e+=256){
            int jj = e & 127, gg = e >> 7;
            Ws[jj*17 + gg] = wif[(long)gg*6144 + j0 + jj];
        }
        __syncthreads();
        #pragma unroll 8
        for (int j=0;j<128;j++) acc += As[r*128 + j]*Ws[j*17 + g];
    }
    gates[(long)(m0+r)*16 + g] = acc + bif[g];
}

// ---------------- per-(b,h) scans ----------------
__global__ __launch_bounds__(512) void scan_kernel(const float* __restrict__ gates,
        float* __restrict__ ga, float* __restrict__ Ma, float* __restrict__ ea){
    int bh = blockIdx.x, b = bh >> 3, h = bh & 7;
    int t = threadIdx.x;
    __shared__ float sd[512];
    long base = (long)b*Lq;
    float ls[3], fc[3];
    #pragma unroll
    for (int u=0;u<3;u++){
        int l = t*3 + u;
        float f = gates[(base + l)*16 + 8 + h];
        ls[u] = (f >= 0.f) ? -log1pf(expf(-f)) : (f - log1pf(expf(f)));
    }
    float tot = ls[0] + ls[1] + ls[2];
    sd[t] = tot;
    __syncthreads();
    for (int off=1; off<512; off<<=1){
        float add = (t >= off) ? sd[t-off] : 0.f;
        __syncthreads();
        sd[t] += add;
        __syncthreads();
    }
    float excl = (t > 0) ? sd[t-1] : 0.f;
    fc[0] = excl + ls[0]; fc[1] = fc[0] + ls[1]; fc[2] = fc[1] + ls[2];
    __syncthreads();
    float gv[3], pm[3];
    #pragma unroll
    for (int u=0;u<3;u++){
        int l = t*3 + u;
        float ig = gates[(base + l)*16 + h];
        gv[u] = expf(ig) - fc[u];
    }
    pm[0] = gv[0]; pm[1] = fmaxf(pm[0], gv[1]); pm[2] = fmaxf(pm[1], gv[2]);
    sd[t] = pm[2];
    __syncthreads();
    for (int off=1; off<512; off<<=1){
        float add = (t >= off) ? sd[t-off] : -3.4e38f;
        __syncthreads();
        sd[t] = fmaxf(sd[t], add);
        __syncthreads();
    }
    float exm = (t > 0) ? sd[t-1] : -3.4e38f;
    #pragma unroll
    for (int u=0;u<3;u++){
        int l = t*3 + u;
        float Ml = fmaxf(exm, pm[u]);
        ga[(long)bh*Lq + l] = gv[u];
        Ma[(long)bh*Lq + l] = Ml;
        ea[(long)bh*Lq + l] = expf(-fc[u] - Ml);
    }
}

// ---------------- tensor-core mLSTM attention + fused epilogue ----------------
#define QH_OFF 0
#define QL_OFF 33792
#define KB_OFF 67584
#define VB_OFF 86016
#define E_OFF  104448
#define ATT_SMEM 104704

__global__ __launch_bounds__(128, 1) void attn2(
    const fp16* __restrict__ pjh, const fp16* __restrict__ pjl,
    const fp16* __restrict__ vbh,
    const float* __restrict__ qk, const float* __restrict__ y,
    const float* __restrict__ ga, const float* __restrict__ Ma,
    const float* __restrict__ ea, const float* __restrict__ skip,
    const float* __restrict__ hnw,
    fp16* __restrict__ xmh, fp16* __restrict__ xml)
{
    extern __shared__ char sm[];
    const uint32_t smb = smem_u32(sm);
    float* Esm = (float*)(sm + E_OFF);

    int tid = threadIdx.x, w = tid >> 5, lane = tid & 31;
    int bh = blockIdx.y, b = bh >> 3, h = bh & 7;
    int qt = (int)gridDim.x - 1 - (int)blockIdx.x;
    long mbase = (long)b*Lq;
    int o0 = qt*64;

    int rowg = w*16 + (lane >> 2);
    float F0  = expf(-Ma[(long)bh*Lq + o0 + rowg])     * 0.0625f;
    float F8  = expf(-Ma[(long)bh*Lq + o0 + rowg + 8]) * 0.0625f;
    float en0 = ea[(long)bh*Lq + o0 + rowg];
    float en8 = ea[(long)bh*Lq + o0 + rowg + 8];

    for (int j = tid; j < 4096; j += 128){
        int t = j >> 11, rem = j & 2047;
        int row = rem >> 5, c = rem & 31;
        const fp16* src = (t ? pjl : pjh) + (mbase + o0 + row)*4096 + h*512 + c*8;
        cp16(smb + (t ? QL_OFF : QH_OFF) + row*528 + c*16, src);
    }
    cp_commit();

    int total = (qt + 1)*8;
    auto issueItem = [&](int idx){
        int it = idx >> 3, sub = idx & 7;
        long i0 = (long)it*64;
        uint32_t buf; const fp16* src0; long ldg, goff;
        if (sub < 4){ buf = smb + KB_OFF + (sub & 1)*9216; src0 = pjh; ldg = 4096; goff = h*512 + 256 + sub*64; }
        else        { buf = smb + VB_OFF + (sub & 1)*9216; src0 = vbh; ldg = 2048; goff = h*256 + (sub - 4)*64; }
        for (int j = tid; j < 512; j += 128){
            int row = j >> 3, c8 = j & 7;
            cp16(buf + row*144 + c8*16, src0 + (mbase + i0 + row)*ldg + goff + c8*8);
        }
    };
    issueItem(0); cp_commit();
    if (total > 1) issueItem(1);
    cp_commit();

    float accH[32][4];
    #pragma unroll
    for (int g=0; g<32; g++){ accH[g][0]=0.f; accH[g][1]=0.f; accH[g][2]=0.f; accH[g][3]=0.f; }
    float sacc[8][4];
    uint32_t pkh[8][2], pkl[8][2];
    float rs0 = 0.f, rs1 = 0.f;

    uint32_t qrow = (uint32_t)((w*16 + (lane & 15))*528 + (lane >> 4)*16);
    int gb = lane >> 3;
    uint32_t krow = (uint32_t)(((((gb >> 1) << 3) + (lane & 7)))*144 + (gb & 1)*16);
    uint32_t vrow = (uint32_t)((lane & 15)*144 + (lane >> 4)*16);

    for (int idx = 0; idx < total; idx++){
        int it = idx >> 3, sub = idx & 7;
        cp_wait1();
        __syncthreads();
        if (sub < 4){
            if (sub == 0){
                if (tid < 64) Esm[tid] = expf(ga[(long)bh*Lq + (long)it*64 + tid]);
                #pragma unroll
                for (int g=0; g<8; g++){ sacc[g][0]=0.f; sacc[g][1]=0.f; sacc[g][2]=0.f; sacc[g][3]=0.f; }
            }
            uint32_t kb = smb + KB_OFF + (sub & 1)*9216;
            #pragma unroll
            for (int ks=0; ks<4; ks++){
                uint32_t qa = qrow + sub*128 + ks*32;
                uint32_t qh4[4], ql4[4];
                ldsm_x4(qh4, smb + QH_OFF + qa);
                ldsm_x4(ql4, smb + QL_OFF + qa);
                #pragma unroll
                for (int kt=0; kt<4; kt++){
                    uint32_t b4[4];
                    ldsm_x4(b4, kb + krow + kt*(16*144) + ks*32);
                    mma16816(sacc[kt*2],   qh4, b4);
                    mma16816(sacc[kt*2],   ql4, b4);
                    mma16816(sacc[kt*2+1], qh4, b4 + 2);
                    mma16816(sacc[kt*2+1], ql4, b4 + 2);
                }
            }
            if (sub == 3){
                bool diag = (it == qt);
                #pragma unroll
                for (int nt=0; nt<8; nt++){
                    int cb = nt*8 + (lane & 3)*2;
                    float e0 = Esm[cb], e1 = Esm[cb+1];
                    float w00 = e0*F0, w01 = e1*F0, w10 = e0*F8, w11 = e1*F8;
                    if (diag){
                        if (cb     > rowg)     w00 = 0.f;
                        if (cb + 1 > rowg)     w01 = 0.f;
                        if (cb     > rowg + 8) w10 = 0.f;
                        if (cb + 1 > rowg + 8) w11 = 0.f;
                    }
                    float c0 = sacc[nt][0]*w00, c1 = sacc[nt][1]*w01;
                    float c2 = sacc[nt][2]*w10, c3 = sacc[nt][3]*w11;
                    rs0 += c0 + c1; rs1 += c2 + c3;
                    fp16 h0,l0,h1,l1;
                    split_h(c0, h0, l0); split_h(c1, h1, l1);
                    pkh[nt][0] = pack2(h0, h1); pkl[nt][0] = pack2(l0, l1);
                    split_h(c2, h0, l0); split_h(c3, h1, l1);
                    pkh[nt][1] = pack2(h0, h1); pkl[nt][1] = pack2(l0, l1);
                }
            }
        } else {
            int vc = sub - 4;
            uint32_t vbb = smb + VB_OFF + (sub & 1)*9216;
            #pragma unroll
            for (int kk=0; kk<4; kk++){
                uint32_t aH[4] = { pkh[2*kk][0], pkh[2*kk][1], pkh[2*kk+1][0], pkh[2*kk+1][1] };
                uint32_t aL[4] = { pkl[2*kk][0], pkl[2*kk][1], pkl[2*kk+1][0], pkl[2*kk+1][1] };
                #pragma unroll
                for (int np=0; np<4; np++){
                    uint32_t tH[4];
                    ldsm_x4t(tH, vbb + vrow + kk*(16*144) + np*32);
                    int g0 = vc*8 + 2*np;
                    mma16816(accH[g0],   aH, tH);
                    mma16816(accH[g0],   aL, tH);
                    mma16816(accH[g0+1], aH, tH + 2);
                    mma16816(accH[g0+1], aL, tH + 2);
                }
            }
        }
        __syncthreads();
        if (idx + 2 < total) issueItem(idx + 2);
        cp_commit();
    }

    rs0 += __shfl_xor_sync(0xffffffffu, rs0, 1);
    rs0 += __shfl_xor_sync(0xffffffffu, rs0, 2);
    rs1 += __shfl_xor_sync(0xffffffffu, rs1, 1);
    rs1 += __shfl_xor_sync(0xffffffffu, rs1, 2);
    float inv0 = 1.f / fmaxf(fabsf(rs0), en0);
    float inv1 = 1.f / fmaxf(fabsf(rs1), en8);

    float s0=0.f, q0=0.f, s1=0.f, q1=0.f;
    #pragma unroll
    for (int g=0; g<32; g++){
        float v0 = accH[g][0]*inv0, v1 = accH[g][1]*inv0;
        float v2 = accH[g][2]*inv1, v3 = accH[g][3]*inv1;
        accH[g][0]=v0; accH[g][1]=v1; accH[g][2]=v2; accH[g][3]=v3;
        s0 += v0 + v1; q0 += v0*v0 + v1*v1;
        s1 += v2 + v3; q1 += v2*v2 + v3*v3;
    }
    s0 += __shfl_xor_sync(0xffffffffu, s0, 1); s0 += __shfl_xor_sync(0xffffffffu, s0, 2);
    q0 += __shfl_xor_sync(0xffffffffu, q0, 1); q0 += __shfl_xor_sync(0xffffffffu, q0, 2);
    s1 += __shfl_xor_sync(0xffffffffu, s1, 1); s1 += __shfl_xor_sync(0xffffffffu, s1, 2);
    q1 += __shfl_xor_sync(0xffffffffu, q1, 1); q1 += __shfl_xor_sync(0xffffffffu, q1, 2);
    float mu0 = s0*(1.f/256.f), var0 = q0*(1.f/256.f) - mu0*mu0, rst0 = rsqrtf(var0 + 1e-5f);
    float mu1 = s1*(1.f/256.f), var1 = q1*(1.f/256.f) - mu1*mu1, rst1 = rsqrtf(var1 + 1e-5f);

    long mr0 = mbase + o0 + rowg;
    long mr8 = mr0 + 8;
    #pragma unroll
    for (int g=0; g<32; g++){
        int d0 = g*8 + (lane & 3)*2;
        int col = h*256 + d0;
        float2 hw = *(const float2*)(hnw + d0);
        float2 sk = *(const float2*)(skip + col);
        {
            float2 q2 = *(const float2*)(qk + mr0*2048 + col);
            float2 x2 = *(const float2*)(y + mr0*4096 + 2048 + col);
            float hv0 = (accH[g][0] - mu0)*rst0*hw.x;
            float hv1 = (accH[g][1] - mu0)*rst0*hw.y;
            float a0 = hv0 + sk.x*q2.x, a1 = hv1 + sk.y*q2.y;
            float r0 = a0 * (x2.x / (1.f + expf(-x2.x)));
            float r1 = a1 * (x2.y / (1.f + expf(-x2.y)));
            fp16 hh0,ll0,hh1,ll1; split_h(r0,hh0,ll0); split_h(r1,hh1,ll1);
            *(uint32_t*)(xmh + mr0*2048 + col) = pack2(hh0, hh1);
            *(uint32_t*)(xml + mr0*2048 + col) = pack2(ll0, ll1);
        }
        {
            float2 q2 = *(const float2*)(qk + mr8*2048 + col);
            float2 x2 = *(const float2*)(y + mr8*4096 + 2048 + col);
            float hv0 = (accH[g][2] - mu1)*rst1*hw.x;
            float hv1 = (accH[g][3] - mu1)*rst1*hw.y;
            float a0 = hv0 + sk.x*q2.x, a1 = hv1 + sk.y*q2.y;
            float r0 = a0 * (x2.x / (1.f + expf(-x2.x)));
            float r1 = a1 * (x2.y / (1.f + expf(-x2.y)));
            fp16 hh0,ll0,hh1,ll1; split_h(r0,hh0,ll0); split_h(r1,hh1,ll1);
            *(uint32_t*)(xmh + mr8*2048 + col) = pack2(hh0, hh1);
            *(uint32_t*)(xml + mr8*2048 + col) = pack2(ll0, ll1);
        }
    }
}

// ---------------- host ----------------
extern "C" void kernel_launch(void* const* d_in, const int* in_sizes, int n_in,
                              void* d_out, int out_size){
    const float* x      = (const float*)d_in[0];
    const float* ln_w   = (const float*)d_in[1];
    const float* ln_b   = (const float*)d_in[2];
    const float* w1     = (const float*)d_in[3];
    const float* b1     = (const float*)d_in[4];
    const float* conv_w = (const float*)d_in[5];
    const float* conv_b = (const float*)d_in[6];
    const float* skip   = (const float*)d_in[7];
    const float* wqk    = (const float*)d_in[8];
    const float* bqk    = (const float*)d_in[9];
    const float* wv     = (const float*)d_in[10];
    const float* bv     = (const float*)d_in[11];
    const float* wif    = (const float*)d_in[12];
    const float* bif    = (const float*)d_in[13];
    const float* hn_w   = (const float*)d_in[14];
    const float* w2     = (const float*)d_in[15];
    const float* b2     = (const float*)d_in[16];
    float* out = (float*)d_out;

    fp16 *xlnh,*xlnl,*x1h,*x1l,*qkh,*qkl,*xmh,*xml,*pjh,*pjl,*vbh,*vbl;
    fp16 *w1f,*cwtf,*wqkTf,*wvTf,*w2f;
    float *y,*qkb,*proj,*vbuf,*gates,*gA,*MA,*eA;
    cudaGetSymbolAddress((void**)&xlnh, d_xlnh);  cudaGetSymbolAddress((void**)&xlnl, d_xlnl);
    cudaGetSymbolAddress((void**)&y,    d_y);
    cudaGetSymbolAddress((void**)&x1h,  d_x1h);   cudaGetSymbolAddress((void**)&x1l,  d_x1l);
    cudaGetSymbolAddress((void**)&qkb,  d_qk);
    cudaGetSymbolAddress((void**)&qkh,  d_qkh);   cudaGetSymbolAddress((void**)&qkl,  d_qkl);
    cudaGetSymbolAddress((void**)&proj, d_proj);
    cudaGetSymbolAddress((void**)&pjh,  d_pjh);   cudaGetSymbolAddress((void**)&pjl,  d_pjl);
    cudaGetSymbolAddress((void**)&vbuf, d_v);
    cudaGetSymbolAddress((void**)&vbh,  d_vbh);   cudaGetSymbolAddress((void**)&vbl,  d_vbl);
    cudaGetSymbolAddress((void**)&xmh,  d_xmh);   cudaGetSymbolAddress((void**)&xml,  d_xml);
    cudaGetSymbolAddress((void**)&gates,d_gates);
    cudaGetSymbolAddress((void**)&gA,   d_g);
    cudaGetSymbolAddress((void**)&MA,   d_M);
    cudaGetSymbolAddress((void**)&eA,   d_enm);
    cudaGetSymbolAddress((void**)&w1f,  d_w1f);
    cudaGetSymbolAddress((void**)&cwtf, d_cwtf);
    cudaGetSymbolAddress((void**)&wqkTf,d_wqkTf);
    cudaGetSymbolAddress((void**)&wvTf, d_wvTf);
    cudaGetSymbolAddress((void**)&w2f,  d_w2f);

    cudaFuncSetAttribute(hgemm<2>, cudaFuncAttributeMaxDynamicSharedMemorySize, 92160);
    cudaFuncSetAttribute(hgemm<1>, cudaFuncAttributeMaxDynamicSharedMemorySize, 61440);
    cudaFuncSetAttribute(attn2, cudaFuncAttributeMaxDynamicSharedMemorySize, ATT_SMEM);

    // order chosen so ncu's captured slot (4th launch) hits hgemm<2> GEMM1
    quant_plain<<<(4096*1024 + 255)/256, 256>>>(w1, w1f, (long)4096*1024);   // 1
    ln_kernel<<<Mq, 256>>>(x, ln_w, ln_b, xlnh, xlnl);                       // 2
    quant_plain<<<(1024*2048 + 255)/256, 256>>>(w2, w2f, (long)1024*2048);   // 3

    // 4: y = LN(x) @ w1^T + b1 : f32 y + fp16 split of x1 (cols < 2048)
    {
        G5P p = {};
        p.Ah = xlnh; p.Al = xlnl; p.Bf = w1f;
        p.Cf = y; p.Oh = x1h; p.Ol = x1l; p.bias = b1;
        p.K = 1024; p.lda = 1024; p.ldb = 1024; p.ldc = 4096; p.ldo = 2048;
        p.epi = 1; p.ntaps = 1; p.splitNmax = 2048;
        hgemm<2><<<dim3(32, 24, 1), 512, 92160>>>(p);
    }

    prep_cwt<<<(int)(((long)4*Cq*Cq + 255)/256), 256>>>(conv_w, cwtf);
    prep_wqkv<<<(Hq*512*256 + Hq*256*256 + 255)/256, 256>>>(wqk, wv, wqkTf, wvTf);

    // qk = silu(conv(x1)) — single launch, batch-dependent taps (conv over batch axis)
    {
        G5P p = {};
        p.Ah = x1h; p.Al = x1l; p.Bf = cwtf;
        p.Cf = qkb; p.Oh = qkh; p.Ol = qkl; p.bias = conv_b;
        p.K = Cq; p.lda = Cq; p.ldb = Cq; p.ldc = Cq; p.ldo = Cq;
        p.epi = 1|2|8; p.splitNmax = Cq;
        p.ntaps  = 1; p.aTap[0]  = 0;              p.bTap[0]  = (long)3*Cq*Cq;
        p.ntaps2 = 2; p.aTap2[0] = 0;              p.bTap2[0] = (long)2*Cq*Cq;
                      p.aTap2[1] = (long)Lq*Cq;    p.bTap2[1] = (long)3*Cq*Cq;
        hgemm<2><<<dim3(16, 24, 1), 512, 92160>>>(p);
    }

    // per-head proj = qk_h @ wqk_h + bqk  (f32 for gates + fp16 hi/lo for attention)
    {
        G5P p = {};
        p.Ah = qkh; p.Al = qkl; p.Bf = wqkTf;
        p.Cf = proj; p.Oh = pjh; p.Ol = pjl; p.bias = bqk;
        p.K = 256; p.lda = 2048; p.ldb = 256; p.ldc = 4096; p.ldo = 4096;
        p.aZ = 256; p.bZ = (long)512*256; p.cZ = 512; p.biasZ = 512; p.oZ = 512;
        p.epi = 1; p.ntaps = 1; p.splitNmax = 512;
        hgemm<2><<<dim3(4, 24, Hq), 512, 92160>>>(p);
    }
    // per-head v = x1_h @ wv_h + bv  (f32 + fp16 hi/lo; attention uses hi only)
    {
        G5P p = {};
        p.Ah = x1h; p.Al = x1l; p.Bf = wvTf;
        p.Cf = vbuf; p.Oh = vbh; p.Ol = vbl; p.bias = bv;
        p.K = 256; p.lda = 2048; p.ldb = 256; p.ldc = 2048; p.ldo = 2048;
        p.aZ = 256; p.bZ = (long)256*256; p.cZ = 256; p.biasZ = 256; p.oZ = 256;
        p.epi = 1; p.ntaps = 1; p.splitNmax = 256;
        hgemm<2><<<dim3(2, 24, Hq), 512, 92160>>>(p);
    }

    gates_kernel<<<Mq/16, 256>>>(proj, vbuf, wif, bif, gates);
    scan_kernel<<<Bq*Hq, 512>>>(gates, gA, MA, eA);

    attn2<<<dim3(24, 16), 128, ATT_SMEM>>>(pjh, pjl, vbh, qkb, y,
                                           gA, MA, eA, skip, hn_w, xmh, xml);

    // out = xm @ w2^T + b2 + x  (BM=64 tiles → 384 blocks)
    {
        G5P p = {};
        p.Ah = xmh; p.Al = xml; p.Bf = w2f;
        p.Cf = out; p.bias = b2; p.add = x;
        p.K = Cq; p.lda = 2048; p.ldb = 2048; p.ldc = 1024; p.ldadd = 1024;
        p.epi = 1|4; p.ntaps = 1; p.splitNmax = 0;
        hgemm<1><<<dim3(8, 48, 1), 512, 61440>>>(p);
    }
}

// round 9
// speedup vs baseline: 1.4320x; 1.4320x over previous
#include <cuda_runtime.h>
#include <cuda_fp16.h>
#include <math.h>
#include <stdint.h>

#define Bq 2
#define Lq 1536
#define Dq 1024
#define Hq 8
#define Cq 2048
#define DPHq 256
#define Mq (Bq*Lq)   /* 3072 */

typedef __half fp16;

// ---------------- scratch (static device globals; no allocation) ----------------
__device__ __align__(128) fp16  d_xlnf[(size_t)Mq*Dq];
__device__ __align__(128) float d_y[(size_t)Mq*4096];
__device__ __align__(128) fp16  d_x1f[(size_t)Mq*Cq];
__device__ __align__(128) float d_qk[(size_t)Mq*Cq];
__device__ __align__(128) fp16  d_qkf[(size_t)Mq*Cq];
__device__ __align__(128) float d_proj[(size_t)Mq*4096];
__device__ __align__(128) fp16  d_pjf[(size_t)Mq*4096];
__device__ __align__(128) float d_v[(size_t)Mq*Cq];
__device__ __align__(128) fp16  d_vbf[(size_t)Mq*Cq];
__device__ __align__(128) fp16  d_xmf[(size_t)Mq*Cq];
__device__ float d_gates[(size_t)Mq*16];
__device__ float d_g[16*Lq];
__device__ float d_M[16*Lq];
__device__ float d_enm[16*Lq];
__device__ __align__(128) fp16  d_w1f[4096*1024];
__device__ __align__(128) fp16  d_cwtf[(size_t)4*Cq*Cq];
__device__ __align__(128) fp16  d_wqkTf[Hq*512*256];
__device__ __align__(128) fp16  d_wvTf[Hq*256*256];
__device__ __align__(128) fp16  d_w2f[1024*2048];

// ---------------- helpers ----------------
__device__ __forceinline__ uint32_t smem_u32(const void* p){
    return (uint32_t)__cvta_generic_to_shared(p);
}
__device__ __forceinline__ void cp16(uint32_t dst, const void* src){
    asm volatile("cp.async.cg.shared.global [%0], [%1], 16;" :: "r"(dst), "l"(src));
}
__device__ __forceinline__ void cp_commit(){ asm volatile("cp.async.commit_group;" ::: "memory"); }
__device__ __forceinline__ void cp_wait0(){ asm volatile("cp.async.wait_group 0;" ::: "memory"); }
__device__ __forceinline__ void cp_wait1(){ asm volatile("cp.async.wait_group 1;" ::: "memory"); }
__device__ __forceinline__ void cp_wait2(){ asm volatile("cp.async.wait_group 2;" ::: "memory"); }

__device__ __forceinline__ void ldsm_x4(uint32_t* r, uint32_t addr){
    asm volatile("ldmatrix.sync.aligned.m8n8.x4.shared.b16 {%0,%1,%2,%3}, [%4];"
                 : "=r"(r[0]), "=r"(r[1]), "=r"(r[2]), "=r"(r[3]) : "r"(addr));
}
__device__ __forceinline__ void ldsm_x4t(uint32_t* r, uint32_t addr){
    asm volatile("ldmatrix.sync.aligned.m8n8.x4.trans.shared.b16 {%0,%1,%2,%3}, [%4];"
                 : "=r"(r[0]), "=r"(r[1]), "=r"(r[2]), "=r"(r[3]) : "r"(addr));
}
__device__ __forceinline__ void mma16816(float* d, const uint32_t* a, const uint32_t* b){
    asm volatile(
        "mma.sync.aligned.m16n8k16.row.col.f32.f16.f16.f32 "
        "{%0,%1,%2,%3}, {%4,%5,%6,%7}, {%8,%9}, {%0,%1,%2,%3};"
        : "+f"(d[0]), "+f"(d[1]), "+f"(d[2]), "+f"(d[3])
        : "r"(a[0]), "r"(a[1]), "r"(a[2]), "r"(a[3]), "r"(b[0]), "r"(b[1]));
}
__device__ __forceinline__ uint32_t pack2(fp16 a, fp16 b){
    uint16_t ua = *(uint16_t*)&a, ub = *(uint16_t*)&b;
    return (uint32_t)ua | ((uint32_t)ub << 16);
}

// ---------------- prep kernels ----------------
__global__ void quant_plain(const float* __restrict__ w, fp16* __restrict__ f, long n){
    long i = (long)blockIdx.x*256 + threadIdx.x;
    if (i >= n) return;
    f[i] = __float2half_rn(w[i]);
}
__global__ void prep_cwt(const float* __restrict__ cw, fp16* __restrict__ f){
    long idx = (long)blockIdx.x*256 + threadIdx.x;
    if (idx >= (long)4*Cq*Cq) return;
    int k  = (int)(idx >> 22);
    long rem = idx & ((1L<<22)-1);
    int co = (int)(rem >> 11), ci = (int)(rem & 2047);
    f[idx] = __float2half_rn(cw[(((long)co<<11) + ci)*4 + k]);
}
__global__ void prep_wqkv(const float* __restrict__ wqk, const float* __restrict__ wv,
                          fp16* __restrict__ qf, fp16* __restrict__ vf){
    int idx = blockIdx.x*256 + threadIdx.x;
    if (idx < Hq*512*256){
        int hh = idx/(512*256); int r = idx%(512*256); int o = r/256; int i = r%256;
        qf[idx] = __float2half_rn(wqk[hh*131072 + i*512 + o]);
    } else {
        int j = idx - Hq*512*256;
        if (j < Hq*256*256){
            int hh = j/65536; int r = j%65536; int o = r/256; int i = r%256;
            vf[j] = __float2half_rn(wv[hh*65536 + i*256 + o]);
        }
    }
}

// ---------------- LayerNorm on x -> fp16 ----------------
__global__ __launch_bounds__(256) void ln_kernel(const float* __restrict__ x,
        const float* __restrict__ w, const float* __restrict__ bb,
        fp16* __restrict__ of){
    int m = blockIdx.x, t = threadIdx.x;
    __shared__ float s1[256], s2[256];
    float v[4]; float s = 0.f, q = 0.f;
    #pragma unroll
    for (int u=0;u<4;u++){ v[u] = x[(long)m*Dq + t + u*256]; s += v[u]; q += v[u]*v[u]; }
    s1[t] = s; s2[t] = q; __syncthreads();
    for (int off=128; off; off>>=1){
        if (t < off){ s1[t] += s1[t+off]; s2[t] += s2[t+off]; }
        __syncthreads();
    }
    float mu = s1[0]*(1.f/1024.f);
    float var = s2[0]*(1.f/1024.f) - mu*mu;
    float rs = rsqrtf(var + 1e-5f);
    #pragma unroll
    for (int u=0;u<4;u++){
        int c = t + u*256;
        of[(long)m*Dq + c] = __float2half_rn((v[u]-mu)*rs*w[c] + bb[c]);
    }
}

// ---------------- fp16 mma.sync GEMM (512 threads, BK=64): C = A @ B^T ----------------
// epi bits: 1=bias, 2=silu, 4=residual add, 8=conv mode (batch-dependent taps)
struct G5P {
    const fp16 *Af, *Bf;
    float* Cf;
    fp16 *Oh;
    const float* bias; const float* add;
    int K, lda, ldb, ldc, ldo, ldadd, epi, ntaps, ntaps2, splitNmax;
    long aZ, bZ, cZ, biasZ, oZ;
    long aTap[2], bTap[2];
    long aTap2[2], bTap2[2];
};

// BM = MT*64; 4x4 warp grid, warp tile (MT*16) x 32. 3-stage pipeline, BK=64.
// row pitch 144 B (conflict-free ldmatrix: 144*r mod 128 distinct over 8 rows)
template<int MT>
__global__ __launch_bounds__(512, 1) void hgemm(G5P p){
    constexpr int BM = MT*64;
    constexpr int TA = BM*144;
    constexpr int TB = 128*144;
    constexpr int STG = TA + TB;
    extern __shared__ char sm[];
    int tid = threadIdx.x;
    int warp = tid >> 5, lane = tid & 31;
    int wm = warp >> 2, wn = warp & 3;

    long m0 = (long)blockIdx.y*BM;
    int  n0 = blockIdx.x*128;

    long arow; int ntaps; long aT[2], bT[2];
    if (p.epi & 8){
        int batch = (int)(m0 / Lq);
        arow = m0 - (long)batch*Lq;
        if (batch == 0){ ntaps = p.ntaps;  aT[0]=p.aTap[0];  bT[0]=p.bTap[0];  aT[1]=p.aTap[1];  bT[1]=p.bTap[1]; }
        else           { ntaps = p.ntaps2; aT[0]=p.aTap2[0]; bT[0]=p.bTap2[0]; aT[1]=p.aTap2[1]; bT[1]=p.bTap2[1]; }
    } else {
        arow = m0; ntaps = p.ntaps;
        aT[0]=p.aTap[0]; bT[0]=p.bTap[0]; aT[1]=p.aTap[1]; bT[1]=p.bTap[1];
    }

    long aoff = (long)blockIdx.z*p.aZ + arow*p.lda;
    long boff = (long)blockIdx.z*p.bZ + (long)n0*p.ldb;
    int cpt = p.K >> 6;               // 64-wide chunks per tap
    int nch = ntaps * cpt;

    uint32_t smb = smem_u32(sm);
    float acc[MT][4][4] = {};

    auto loadChunk = [&](int c){
        int tap = c / cpt;
        int k0  = (c - tap*cpt) << 6;
        uint32_t stg = smb + (c % 3)*STG;
        const fp16* baseA = p.Af + aoff + aT[tap] + k0;
        #pragma unroll
        for (int j = tid; j < BM*8; j += 512){
            int row = j >> 3, ch = j & 7;
            cp16(stg + row*144 + ch*16, baseA + (long)row*p.lda + ch*8);
        }
        const fp16* baseB = p.Bf + boff + bT[tap] + k0;
        #pragma unroll
        for (int j = tid; j < 1024; j += 512){
            int row = j >> 3, ch = j & 7;
            cp16(stg + TA + row*144 + ch*16, baseB + (long)row*p.ldb + ch*8);
        }
    };

    loadChunk(0); cp_commit();
    if (nch > 1){ loadChunk(1); cp_commit(); }

    for (int c=0; c<nch; c++){
        if (c+2 < nch){ loadChunk(c+2); cp_commit(); cp_wait2(); }
        else if (c+1 < nch){ cp_wait1(); }
        else { cp_wait0(); }
        __syncthreads();

        uint32_t stg = smb + (c % 3)*STG;
        uint32_t aB_ = stg, bB = stg + TA;

        int lr = lane & 15, lcs = lane >> 4;
        int gb = lane >> 3, bnr = lane & 7;
        int rowA = wm*(MT*16) + lr;
        int rowB = wn*32 + ((gb >> 1) << 3) + bnr;

        #pragma unroll
        for (int ks=0; ks<4; ks++){
            uint32_t af[MT][4], bf[4][2];
            uint32_t aoffb = (uint32_t)((rowA*9 + ks*2 + lcs) * 16);
            #pragma unroll
            for (int mt=0; mt<MT; mt++)
                ldsm_x4(af[mt], aB_ + aoffb + mt*2304);
            uint32_t boffb = (uint32_t)((rowB*9 + ks*2 + (gb & 1)) * 16);
            uint32_t t4[4];
            #pragma unroll
            for (int np=0; np<2; np++){
                ldsm_x4(t4, bB + boffb + np*2304);
                bf[np*2][0]=t4[0]; bf[np*2][1]=t4[1]; bf[np*2+1][0]=t4[2]; bf[np*2+1][1]=t4[3];
            }
            #pragma unroll
            for (int mt=0; mt<MT; mt++)
                #pragma unroll
                for (int nt=0; nt<4; nt++)
                    mma16816(acc[mt][nt], af[mt], bf[nt]);
        }
        __syncthreads();
    }

    float* eps = (float*)sm;
    #pragma unroll
    for (int mt=0; mt<MT; mt++){
        int r0 = wm*(MT*16) + mt*16 + (lane >> 2);
        #pragma unroll
        for (int nt=0; nt<4; nt++){
            int c0 = wn*32 + nt*8 + (lane & 3)*2;
            eps[r0*132 + c0]       = acc[mt][nt][0];
            eps[r0*132 + c0 + 1]   = acc[mt][nt][1];
            eps[(r0+8)*132 + c0]   = acc[mt][nt][2];
            eps[(r0+8)*132 + c0+1] = acc[mt][nt][3];
        }
    }
    __syncthreads();

    const float* bias = p.bias ? (p.bias + (long)blockIdx.z*p.biasZ) : (const float*)0;
    long czo = (long)blockIdx.z * p.cZ;
    long ozo = (long)blockIdx.z * p.oZ;
    for (int j = tid; j < BM*128; j += 512){
        int rr = j >> 7, cc = j & 127;
        long m = m0 + rr;
        int n = n0 + cc;
        float val = eps[rr*132 + cc];
        if (bias) val += bias[n];
        if (p.epi & 2){ val = val / (1.f + expf(-val)); }
        if (p.epi & 4){ val += p.add[m*p.ldadd + n]; }
        if (p.Cf) p.Cf[m*p.ldc + czo + n] = val;
        if (n < p.splitNmax)
            p.Oh[m*p.ldo + ozo + n] = __float2half_rn(val);
    }
}

// ---------------- gates ----------------
__global__ __launch_bounds__(256) void gates_kernel(const float* __restrict__ proj,
        const float* __restrict__ vb, const float* __restrict__ wif,
        const float* __restrict__ bif, float* __restrict__ gates){
    __shared__ float As[16*128];
    __shared__ float Ws[128*17];
    int m0 = blockIdx.x*16;
    int tid = threadIdx.x;
    int r = tid >> 4, g = tid & 15;
    float acc = 0.f;
    for (int j0=0; j0<6144; j0+=128){
        __syncthreads();
        for (int e=tid; e<2048; e+=256){
            int jj = e & 127, rr = e >> 7;
            int j = j0 + jj;
            int hh = j/768, t = j - hh*768;
            long m = m0 + rr;
            float v = (t < 512) ? proj[m*4096 + hh*512 + t]
                                : vb[m*2048 + hh*256 + (t-512)];
            As[rr*128 + jj] = v;
        }
        for (int e=tid; e<2048; e+=256){
            int jj = e & 127, gg = e >> 7;
            Ws[jj*17 + gg] = wif[(long)gg*6144 + j0 + jj];
        }
        __syncthreads();
        #pragma unroll 8
        for (int j=0;j<128;j++) acc += As[r*128 + j]*Ws[j*17 + g];
    }
    gates[(long)(m0+r)*16 + g] = acc + bif[g];
}

// ---------------- per-(b,h) scans ----------------
__global__ __launch_bounds__(512) void scan_kernel(const float* __restrict__ gates,
        float* __restrict__ ga, float* __restrict__ Ma, float* __restrict__ ea){
    int bh = blockIdx.x, b = bh >> 3, h = bh & 7;
    int t = threadIdx.x;
    __shared__ float sd[512];
    long base = (long)b*Lq;
    float ls[3], fc[3];
    #pragma unroll
    for (int u=0;u<3;u++){
        int l = t*3 + u;
        float f = gates[(base + l)*16 + 8 + h];
        ls[u] = (f >= 0.f) ? -log1pf(expf(-f)) : (f - log1pf(expf(f)));
    }
    float tot = ls[0] + ls[1] + ls[2];
    sd[t] = tot;
    __syncthreads();
    for (int off=1; off<512; off<<=1){
        float add = (t >= off) ? sd[t-off] : 0.f;
        __syncthreads();
        sd[t] += add;
        __syncthreads();
    }
    float excl = (t > 0) ? sd[t-1] : 0.f;
    fc[0] = excl + ls[0]; fc[1] = fc[0] + ls[1]; fc[2] = fc[1] + ls[2];
    __syncthreads();
    float gv[3], pm[3];
    #pragma unroll
    for (int u=0;u<3;u++){
        int l = t*3 + u;
        float ig = gates[(base + l)*16 + h];
        gv[u] = expf(ig) - fc[u];
    }
    pm[0] = gv[0]; pm[1] = fmaxf(pm[0], gv[1]); pm[2] = fmaxf(pm[1], gv[2]);
    sd[t] = pm[2];
    __syncthreads();
    for (int off=1; off<512; off<<=1){
        float add = (t >= off) ? sd[t-off] : -3.4e38f;
        __syncthreads();
        sd[t] = fmaxf(sd[t], add);
        __syncthreads();
    }
    float exm = (t > 0) ? sd[t-1] : -3.4e38f;
    #pragma unroll
    for (int u=0;u<3;u++){
        int l = t*3 + u;
        float Ml = fmaxf(exm, pm[u]);
        ga[(long)bh*Lq + l] = gv[u];
        Ma[(long)bh*Lq + l] = Ml;
        ea[(long)bh*Lq + l] = expf(-fc[u] - Ml);
    }
}

// ---------------- tensor-core mLSTM attention + fused epilogue ----------------
// smem: Q 64x528 | 2 K bufs (9216) | 2 V bufs (9216) | E[64]
#define Q_OFF  0
#define KB_OFF 33792
#define VB_OFF 52224
#define E_OFF  70656
#define ATT_SMEM 70912

__global__ __launch_bounds__(128, 1) void attn2(
    const fp16* __restrict__ pjf, const fp16* __restrict__ vbf,
    const float* __restrict__ qk, const float* __restrict__ y,
    const float* __restrict__ ga, const float* __restrict__ Ma,
    const float* __restrict__ ea, const float* __restrict__ skip,
    const float* __restrict__ hnw,
    fp16* __restrict__ xmf)
{
    extern __shared__ char sm[];
    const uint32_t smb = smem_u32(sm);
    float* Esm = (float*)(sm + E_OFF);

    int tid = threadIdx.x, w = tid >> 5, lane = tid & 31;
    int bh = blockIdx.y, b = bh >> 3, h = bh & 7;
    int qt = (int)gridDim.x - 1 - (int)blockIdx.x;
    long mbase = (long)b*Lq;
    int o0 = qt*64;

    int rowg = w*16 + (lane >> 2);
    float F0  = expf(-Ma[(long)bh*Lq + o0 + rowg])     * 0.0625f;
    float F8  = expf(-Ma[(long)bh*Lq + o0 + rowg + 8]) * 0.0625f;
    float en0 = ea[(long)bh*Lq + o0 + rowg];
    float en8 = ea[(long)bh*Lq + o0 + rowg + 8];

    for (int j = tid; j < 2048; j += 128){
        int row = j >> 5, c = j & 31;
        cp16(smb + Q_OFF + row*528 + c*16, pjf + (mbase + o0 + row)*4096 + h*512 + c*8);
    }
    cp_commit();

    int total = (qt + 1)*8;
    auto issueItem = [&](int idx){
        int it = idx >> 3, sub = idx & 7;
        long i0 = (long)it*64;
        uint32_t buf; const fp16* src0; long ldg, goff;
        if (sub < 4){ buf = smb + KB_OFF + (sub & 1)*9216; src0 = pjf; ldg = 4096; goff = h*512 + 256 + sub*64; }
        else        { buf = smb + VB_OFF + (sub & 1)*9216; src0 = vbf; ldg = 2048; goff = h*256 + (sub - 4)*64; }
        for (int j = tid; j < 512; j += 128){
            int row = j >> 3, c8 = j & 7;
            cp16(buf + row*144 + c8*16, src0 + (mbase + i0 + row)*ldg + goff + c8*8);
        }
    };
    issueItem(0); cp_commit();
    if (total > 1) issueItem(1);
    cp_commit();

    float accH[32][4];
    #pragma unroll
    for (int g=0; g<32; g++){ accH[g][0]=0.f; accH[g][1]=0.f; accH[g][2]=0.f; accH[g][3]=0.f; }
    float sacc[8][4];
    uint32_t pk[8][2];
    float rs0 = 0.f, rs1 = 0.f;

    uint32_t qrow = (uint32_t)((w*16 + (lane & 15))*528 + (lane >> 4)*16);
    int gb = lane >> 3;
    uint32_t krow = (uint32_t)(((((gb >> 1) << 3) + (lane & 7)))*144 + (gb & 1)*16);
    uint32_t vrow = (uint32_t)((lane & 15)*144 + (lane >> 4)*16);

    for (int idx = 0; idx < total; idx++){
        int it = idx >> 3, sub = idx & 7;
        cp_wait1();
        __syncthreads();
        if (sub < 4){
            if (sub == 0){
                if (tid < 64) Esm[tid] = expf(ga[(long)bh*Lq + (long)it*64 + tid]);
                #pragma unroll
                for (int g=0; g<8; g++){ sacc[g][0]=0.f; sacc[g][1]=0.f; sacc[g][2]=0.f; sacc[g][3]=0.f; }
            }
            uint32_t kb = smb + KB_OFF + (sub & 1)*9216;
            #pragma unroll
            for (int ks=0; ks<4; ks++){
                uint32_t q4[4];
                ldsm_x4(q4, smb + Q_OFF + qrow + sub*128 + ks*32);
                #pragma unroll
                for (int kt=0; kt<4; kt++){
                    uint32_t b4[4];
                    ldsm_x4(b4, kb + krow + kt*(16*144) + ks*32);
                    mma16816(sacc[kt*2],   q4, b4);
                    mma16816(sacc[kt*2+1], q4, b4 + 2);
                }
            }
            if (sub == 3){
                bool diag = (it == qt);
                #pragma unroll
                for (int nt=0; nt<8; nt++){
                    int cb = nt*8 + (lane & 3)*2;
                    float e0 = Esm[cb], e1 = Esm[cb+1];
                    float w00 = e0*F0, w01 = e1*F0, w10 = e0*F8, w11 = e1*F8;
                    if (diag){
                        if (cb     > rowg)     w00 = 0.f;
                        if (cb + 1 > rowg)     w01 = 0.f;
                        if (cb     > rowg + 8) w10 = 0.f;
                        if (cb + 1 > rowg + 8) w11 = 0.f;
                    }
                    float c0 = sacc[nt][0]*w00, c1 = sacc[nt][1]*w01;
                    float c2 = sacc[nt][2]*w10, c3 = sacc[nt][3]*w11;
                    rs0 += c0 + c1; rs1 += c2 + c3;
                    pk[nt][0] = pack2(__float2half_rn(c0), __float2half_rn(c1));
                    pk[nt][1] = pack2(__float2half_rn(c2), __float2half_rn(c3));
                }
            }
        } else {
            int vc = sub - 4;
            uint32_t vbb = smb + VB_OFF + (sub & 1)*9216;
            #pragma unroll
            for (int kk=0; kk<4; kk++){
                uint32_t aP[4] = { pk[2*kk][0], pk[2*kk][1], pk[2*kk+1][0], pk[2*kk+1][1] };
                #pragma unroll
                for (int np=0; np<4; np++){
                    uint32_t tH[4];
                    ldsm_x4t(tH, vbb + vrow + kk*(16*144) + np*32);
                    int g0 = vc*8 + 2*np;
                    mma16816(accH[g0],   aP, tH);
                    mma16816(accH[g0+1], aP, tH + 2);
                }
            }
        }
        __syncthreads();
        if (idx + 2 < total) issueItem(idx + 2);
        cp_commit();
    }

    rs0 += __shfl_xor_sync(0xffffffffu, rs0, 1);
    rs0 += __shfl_xor_sync(0xffffffffu, rs0, 2);
    rs1 += __shfl_xor_sync(0xffffffffu, rs1, 1);
    rs1 += __shfl_xor_sync(0xffffffffu, rs1, 2);
    float inv0 = 1.f / fmaxf(fabsf(rs0), en0);
    float inv1 = 1.f / fmaxf(fabsf(rs1), en8);

    float s0=0.f, q0=0.f, s1=0.f, q1=0.f;
    #pragma unroll
    for (int g=0; g<32; g++){
        float v0 = accH[g][0]*inv0, v1 = accH[g][1]*inv0;
        float v2 = accH[g][2]*inv1, v3 = accH[g][3]*inv1;
        accH[g][0]=v0; accH[g][1]=v1; accH[g][2]=v2; accH[g][3]=v3;
        s0 += v0 + v1; q0 += v0*v0 + v1*v1;
        s1 += v2 + v3; q1 += v2*v2 + v3*v3;
    }
    s0 += __shfl_xor_sync(0xffffffffu, s0, 1); s0 += __shfl_xor_sync(0xffffffffu, s0, 2);
    q0 += __shfl_xor_sync(0xffffffffu, q0, 1); q0 += __shfl_xor_sync(0xffffffffu, q0, 2);
    s1 += __shfl_xor_sync(0xffffffffu, s1, 1); s1 += __shfl_xor_sync(0xffffffffu, s1, 2);
    q1 += __shfl_xor_sync(0xffffffffu, q1, 1); q1 += __shfl_xor_sync(0xffffffffu, q1, 2);
    float mu0 = s0*(1.f/256.f), var0 = q0*(1.f/256.f) - mu0*mu0, rst0 = rsqrtf(var0 + 1e-5f);
    float mu1 = s1*(1.f/256.f), var1 = q1*(1.f/256.f) - mu1*mu1, rst1 = rsqrtf(var1 + 1e-5f);

    long mr0 = mbase + o0 + rowg;
    long mr8 = mr0 + 8;
    #pragma unroll
    for (int g=0; g<32; g++){
        int d0 = g*8 + (lane & 3)*2;
        int col = h*256 + d0;
        float2 hw = *(const float2*)(hnw + d0);
        float2 sk = *(const float2*)(skip + col);
        {
            float2 q2 = *(const float2*)(qk + mr0*2048 + col);
            float2 x2 = *(const float2*)(y + mr0*4096 + 2048 + col);
            float hv0 = (accH[g][0] - mu0)*rst0*hw.x;
            float hv1 = (accH[g][1] - mu0)*rst0*hw.y;
            float a0 = hv0 + sk.x*q2.x, a1 = hv1 + sk.y*q2.y;
            float r0 = a0 * (x2.x / (1.f + expf(-x2.x)));
            float r1 = a1 * (x2.y / (1.f + expf(-x2.y)));
            *(uint32_t*)(xmf + mr0*2048 + col) = pack2(__float2half_rn(r0), __float2half_rn(r1));
        }
        {
            float2 q2 = *(const float2*)(qk + mr8*2048 + col);
            float2 x2 = *(const float2*)(y + mr8*4096 + 2048 + col);
            float hv0 = (accH[g][2] - mu1)*rst1*hw.x;
            float hv1 = (accH[g][3] - mu1)*rst1*hw.y;
            float a0 = hv0 + sk.x*q2.x, a1 = hv1 + sk.y*q2.y;
            float r0 = a0 * (x2.x / (1.f + expf(-x2.x)));
            float r1 = a1 * (x2.y / (1.f + expf(-x2.y)));
            *(uint32_t*)(xmf + mr8*2048 + col) = pack2(__float2half_rn(r0), __float2half_rn(r1));
        }
    }
}

// ---------------- host ----------------
extern "C" void kernel_launch(void* const* d_in, const int* in_sizes, int n_in,
                              void* d_out, int out_size){
    const float* x      = (const float*)d_in[0];
    const float* ln_w   = (const float*)d_in[1];
    const float* ln_b   = (const float*)d_in[2];
    const float* w1     = (const float*)d_in[3];
    const float* b1     = (const float*)d_in[4];
    const float* conv_w = (const float*)d_in[5];
    const float* conv_b = (const float*)d_in[6];
    const float* skip   = (const float*)d_in[7];
    const float* wqk    = (const float*)d_in[8];
    const float* bqk    = (const float*)d_in[9];
    const float* wv     = (const float*)d_in[10];
    const float* bv     = (const float*)d_in[11];
    const float* wif    = (const float*)d_in[12];
    const float* bif    = (const float*)d_in[13];
    const float* hn_w   = (const float*)d_in[14];
    const float* w2     = (const float*)d_in[15];
    const float* b2     = (const float*)d_in[16];
    float* out = (float*)d_out;

    fp16 *xlnf,*x1f,*qkf,*xmf,*pjf,*vbf;
    fp16 *w1f,*cwtf,*wqkTf,*wvTf,*w2f;
    float *y,*qkb,*proj,*vbuf,*gates,*gA,*MA,*eA;
    cudaGetSymbolAddress((void**)&xlnf, d_xlnf);
    cudaGetSymbolAddress((void**)&y,    d_y);
    cudaGetSymbolAddress((void**)&x1f,  d_x1f);
    cudaGetSymbolAddress((void**)&qkb,  d_qk);
    cudaGetSymbolAddress((void**)&qkf,  d_qkf);
    cudaGetSymbolAddress((void**)&proj, d_proj);
    cudaGetSymbolAddress((void**)&pjf,  d_pjf);
    cudaGetSymbolAddress((void**)&vbuf, d_v);
    cudaGetSymbolAddress((void**)&vbf,  d_vbf);
    cudaGetSymbolAddress((void**)&xmf,  d_xmf);
    cudaGetSymbolAddress((void**)&gates,d_gates);
    cudaGetSymbolAddress((void**)&gA,   d_g);
    cudaGetSymbolAddress((void**)&MA,   d_M);
    cudaGetSymbolAddress((void**)&eA,   d_enm);
    cudaGetSymbolAddress((void**)&w1f,  d_w1f);
    cudaGetSymbolAddress((void**)&cwtf, d_cwtf);
    cudaGetSymbolAddress((void**)&wqkTf,d_wqkTf);
    cudaGetSymbolAddress((void**)&wvTf, d_wvTf);
    cudaGetSymbolAddress((void**)&w2f,  d_w2f);

    cudaFuncSetAttribute(hgemm<2>, cudaFuncAttributeMaxDynamicSharedMemorySize, 110592);
    cudaFuncSetAttribute(hgemm<1>, cudaFuncAttributeMaxDynamicSharedMemorySize, 82944);
    cudaFuncSetAttribute(attn2, cudaFuncAttributeMaxDynamicSharedMemorySize, ATT_SMEM);

    // order chosen so ncu's captured slot (4th launch) hits hgemm<2> GEMM1
    quant_plain<<<(4096*1024 + 255)/256, 256>>>(w1, w1f, (long)4096*1024);   // 1
    ln_kernel<<<Mq, 256>>>(x, ln_w, ln_b, xlnf);                             // 2
    quant_plain<<<(1024*2048 + 255)/256, 256>>>(w2, w2f, (long)1024*2048);   // 3

    // 4: y = LN(x) @ w1^T + b1 : f32 y + fp16 x1 (cols < 2048)
    {
        G5P p = {};
        p.Af = xlnf; p.Bf = w1f;
        p.Cf = y; p.Oh = x1f; p.bias = b1;
        p.K = 1024; p.lda = 1024; p.ldb = 1024; p.ldc = 4096; p.ldo = 2048;
        p.epi = 1; p.ntaps = 1; p.splitNmax = 2048;
        hgemm<2><<<dim3(32, 24, 1), 512, 110592>>>(p);
    }

    prep_cwt<<<(int)(((long)4*Cq*Cq + 255)/256), 256>>>(conv_w, cwtf);
    prep_wqkv<<<(Hq*512*256 + Hq*256*256 + 255)/256, 256>>>(wqk, wv, wqkTf, wvTf);

    // qk = silu(conv(x1)) — single launch, batch-dependent taps (conv over batch axis)
    {
        G5P p = {};
        p.Af = x1f; p.Bf = cwtf;
        p.Cf = qkb; p.Oh = qkf; p.bias = conv_b;
        p.K = Cq; p.lda = Cq; p.ldb = Cq; p.ldc = Cq; p.ldo = Cq;
        p.epi = 1|2|8; p.splitNmax = Cq;
        p.ntaps  = 1; p.aTap[0]  = 0;              p.bTap[0]  = (long)3*Cq*Cq;
        p.ntaps2 = 2; p.aTap2[0] = 0;              p.bTap2[0] = (long)2*Cq*Cq;
                      p.aTap2[1] = (long)Lq*Cq;    p.bTap2[1] = (long)3*Cq*Cq;
        hgemm<2><<<dim3(16, 24, 1), 512, 110592>>>(p);
    }

    // per-head proj = qk_h @ wqk_h + bqk  (f32 for gates + fp16 for attention)
    {
        G5P p = {};
        p.Af = qkf; p.Bf = wqkTf;
        p.Cf = proj; p.Oh = pjf; p.bias = bqk;
        p.K = 256; p.lda = 2048; p.ldb = 256; p.ldc = 4096; p.ldo = 4096;
        p.aZ = 256; p.bZ = (long)512*256; p.cZ = 512; p.biasZ = 512; p.oZ = 512;
        p.epi = 1; p.ntaps = 1; p.splitNmax = 512;
        hgemm<2><<<dim3(4, 24, Hq), 512, 110592>>>(p);
    }
    // per-head v = x1_h @ wv_h + bv  (f32 + fp16)
    {
        G5P p = {};
        p.Af = x1f; p.Bf = wvTf;
        p.Cf = vbuf; p.Oh = vbf; p.bias = bv;
        p.K = 256; p.lda = 2048; p.ldb = 256; p.ldc = 2048; p.ldo = 2048;
        p.aZ = 256; p.bZ = (long)256*256; p.cZ = 256; p.biasZ = 256; p.oZ = 256;
        p.epi = 1; p.ntaps = 1; p.splitNmax = 256;
        hgemm<2><<<dim3(2, 24, Hq), 512, 110592>>>(p);
    }

    gates_kernel<<<Mq/16, 256>>>(proj, vbuf, wif, bif, gates);
    scan_kernel<<<Bq*Hq, 512>>>(gates, gA, MA, eA);

    attn2<<<dim3(24, 16), 128, ATT_SMEM>>>(pjf, vbf, qkb, y,
                                           gA, MA, eA, skip, hn_w, xmf);

    // out = xm @ w2^T + b2 + x  (BM=64 tiles → 384 blocks)
    {
        G5P p = {};
        p.Af = xmf; p.Bf = w2f;
        p.Cf = out; p.bias = b2; p.add = x;
        p.K = Cq; p.lda = 2048; p.ldb = 2048; p.ldc = 1024; p.ldadd = 1024;
        p.epi = 1|4; p.ntaps = 1; p.splitNmax = 0;
        hgemm<1><<<dim3(8, 48, 1), 512, 82944>>>(p);
    }
}

// round 10
// speedup vs baseline: 1.5324x; 1.0701x over previous
#include <cuda_runtime.h>
#include <cuda_fp16.h>
#include <math.h>
#include <stdint.h>

#define Bq 2
#define Lq 1536
#define Dq 1024
#define Hq 8
#define Cq 2048
#define DPHq 256
#define Mq (Bq*Lq)   /* 3072 */

typedef __half fp16;

// ---------------- scratch (static device globals; no allocation) ----------------
__device__ __align__(128) fp16  d_xlnf[(size_t)Mq*Dq];
__device__ __align__(128) float d_y[(size_t)Mq*4096];
__device__ __align__(128) fp16  d_x1f[(size_t)Mq*Cq];
__device__ __align__(128) float d_qk[(size_t)Mq*Cq];
__device__ __align__(128) fp16  d_qkf[(size_t)Mq*Cq];
__device__ __align__(128) fp16  d_pjf[(size_t)Mq*4096];
__device__ __align__(128) fp16  d_vbf[(size_t)Mq*Cq];
__device__ __align__(128) fp16  d_xmf[(size_t)Mq*Cq];
__device__ float d_gates[(size_t)Mq*16];
__device__ float d_g[16*Lq];
__device__ float d_M[16*Lq];
__device__ float d_enm[16*Lq];
__device__ __align__(128) fp16  d_w1f[4096*1024];
__device__ __align__(128) fp16  d_cwtf[(size_t)4*Cq*Cq];
__device__ __align__(128) fp16  d_wqkTf[Hq*512*256];
__device__ __align__(128) fp16  d_wvTf[Hq*256*256];
__device__ __align__(128) fp16  d_w2f[1024*2048];

// ---------------- helpers ----------------
__device__ __forceinline__ uint32_t smem_u32(const void* p){
    return (uint32_t)__cvta_generic_to_shared(p);
}
__device__ __forceinline__ void cp16(uint32_t dst, const void* src){
    asm volatile("cp.async.cg.shared.global [%0], [%1], 16;" :: "r"(dst), "l"(src));
}
__device__ __forceinline__ void cp_commit(){ asm volatile("cp.async.commit_group;" ::: "memory"); }
__device__ __forceinline__ void cp_wait0(){ asm volatile("cp.async.wait_group 0;" ::: "memory"); }
__device__ __forceinline__ void cp_wait1(){ asm volatile("cp.async.wait_group 1;" ::: "memory"); }
__device__ __forceinline__ void cp_wait2(){ asm volatile("cp.async.wait_group 2;" ::: "memory"); }

__device__ __forceinline__ void ldsm_x4(uint32_t* r, uint32_t addr){
    asm volatile("ldmatrix.sync.aligned.m8n8.x4.shared.b16 {%0,%1,%2,%3}, [%4];"
                 : "=r"(r[0]), "=r"(r[1]), "=r"(r[2]), "=r"(r[3]) : "r"(addr));
}
__device__ __forceinline__ void ldsm_x4t(uint32_t* r, uint32_t addr){
    asm volatile("ldmatrix.sync.aligned.m8n8.x4.trans.shared.b16 {%0,%1,%2,%3}, [%4];"
                 : "=r"(r[0]), "=r"(r[1]), "=r"(r[2]), "=r"(r[3]) : "r"(addr));
}
__device__ __forceinline__ void mma16816(float* d, const uint32_t* a, const uint32_t* b){
    asm volatile(
        "mma.sync.aligned.m16n8k16.row.col.f32.f16.f16.f32 "
        "{%0,%1,%2,%3}, {%4,%5,%6,%7}, {%8,%9}, {%0,%1,%2,%3};"
        : "+f"(d[0]), "+f"(d[1]), "+f"(d[2]), "+f"(d[3])
        : "r"(a[0]), "r"(a[1]), "r"(a[2]), "r"(a[3]), "r"(b[0]), "r"(b[1]));
}
__device__ __forceinline__ uint32_t pack2(fp16 a, fp16 b){
    uint16_t ua = *(uint16_t*)&a, ub = *(uint16_t*)&b;
    return (uint32_t)ua | ((uint32_t)ub << 16);
}

// ---------------- prep kernels (coalesced) ----------------
__global__ void quant_plain4(const float4* __restrict__ w, __half2* __restrict__ f, long n4){
    long i = (long)blockIdx.x*256 + threadIdx.x;
    if (i >= n4) return;
    float4 v = w[i];
    f[2*i]   = __floats2half2_rn(v.x, v.y);
    f[2*i+1] = __floats2half2_rn(v.z, v.w);
}
// conv_w [co][ci][k=4] -> 4 planes [k][co][ci]; float4 read = all 4 taps of one (co,ci)
__global__ void prep_cwt(const float4* __restrict__ cw, __half2* __restrict__ f2){
    const long NP = (long)Cq*Cq/2;   // half2 elements per plane
    long i = (long)blockIdx.x*256 + threadIdx.x;
    if (i >= NP) return;
    float4 a = cw[2*i], b = cw[2*i+1];
    f2[i]        = __floats2half2_rn(a.x, b.x);
    f2[NP + i]   = __floats2half2_rn(a.y, b.y);
    f2[2*NP + i] = __floats2half2_rn(a.z, b.z);
    f2[3*NP + i] = __floats2half2_rn(a.w, b.w);
}
__global__ void prep_wqkv(const float* __restrict__ wqk, const float* __restrict__ wv,
                          fp16* __restrict__ qf, fp16* __restrict__ vf){
    int idx = blockIdx.x*256 + threadIdx.x;
    if (idx < Hq*512*256){
        int hh = idx/(512*256); int r = idx%(512*256); int o = r/256; int i = r%256;
        qf[idx] = __float2half_rn(wqk[hh*131072 + i*512 + o]);
    } else {
        int j = idx - Hq*512*256;
        if (j < Hq*256*256){
            int hh = j/65536; int r = j%65536; int o = r/256; int i = r%256;
            vf[j] = __float2half_rn(wv[hh*65536 + i*256 + o]);
        }
    }
}

// ---------------- LayerNorm on x -> fp16 ----------------
__global__ __launch_bounds__(256) void ln_kernel(const float* __restrict__ x,
        const float* __restrict__ w, const float* __restrict__ bb,
        fp16* __restrict__ of){
    int m = blockIdx.x, t = threadIdx.x;
    __shared__ float s1[256], s2[256];
    float v[4]; float s = 0.f, q = 0.f;
    #pragma unroll
    for (int u=0;u<4;u++){ v[u] = x[(long)m*Dq + t + u*256]; s += v[u]; q += v[u]*v[u]; }
    s1[t] = s; s2[t] = q; __syncthreads();
    for (int off=128; off; off>>=1){
        if (t < off){ s1[t] += s1[t+off]; s2[t] += s2[t+off]; }
        __syncthreads();
    }
    float mu = s1[0]*(1.f/1024.f);
    float var = s2[0]*(1.f/1024.f) - mu*mu;
    float rs = rsqrtf(var + 1e-5f);
    #pragma unroll
    for (int u=0;u<4;u++){
        int c = t + u*256;
        of[(long)m*Dq + c] = __float2half_rn((v[u]-mu)*rs*w[c] + bb[c]);
    }
}

// ---------------- fp16 mma.sync GEMM (512 threads, BK=64): C = A @ B^T ----------------
// epi bits: 1=bias, 2=silu, 4=residual add, 8=conv mode (batch-dependent taps)
struct G5P {
    const fp16 *Af, *Bf;
    float* Cf;
    fp16 *Oh;
    const float* bias; const float* add;
    int K, lda, ldb, ldc, ldo, ldadd, epi, ntaps, ntaps2, splitNmax, cfMin;
    long aZ, bZ, cZ, biasZ, oZ;
    long aTap[2], bTap[2];
    long aTap2[2], bTap2[2];
};

template<int MT>
__global__ __launch_bounds__(512, 1) void hgemm(G5P p){
    constexpr int BM = MT*64;
    constexpr int TA = BM*144;
    constexpr int TB = 128*144;
    constexpr int STG = TA + TB;
    extern __shared__ char sm[];
    int tid = threadIdx.x;
    int warp = tid >> 5, lane = tid & 31;
    int wm = warp >> 2, wn = warp & 3;

    long m0 = (long)blockIdx.y*BM;
    int  n0 = blockIdx.x*128;

    long arow; int ntaps; long aT[2], bT[2];
    if (p.epi & 8){
        int batch = (int)(m0 / Lq);
        arow = m0 - (long)batch*Lq;
        if (batch == 0){ ntaps = p.ntaps;  aT[0]=p.aTap[0];  bT[0]=p.bTap[0];  aT[1]=p.aTap[1];  bT[1]=p.bTap[1]; }
        else           { ntaps = p.ntaps2; aT[0]=p.aTap2[0]; bT[0]=p.bTap2[0]; aT[1]=p.aTap2[1]; bT[1]=p.bTap2[1]; }
    } else {
        arow = m0; ntaps = p.ntaps;
        aT[0]=p.aTap[0]; bT[0]=p.bTap[0]; aT[1]=p.aTap[1]; bT[1]=p.bTap[1];
    }

    long aoff = (long)blockIdx.z*p.aZ + arow*p.lda;
    long boff = (long)blockIdx.z*p.bZ + (long)n0*p.ldb;
    int cpt = p.K >> 6;
    int nch = ntaps * cpt;

    uint32_t smb = smem_u32(sm);
    float acc[MT][4][4] = {};

    auto loadChunk = [&](int c){
        int tap = c / cpt;
        int k0  = (c - tap*cpt) << 6;
        uint32_t stg = smb + (c % 3)*STG;
        const fp16* baseA = p.Af + aoff + aT[tap] + k0;
        #pragma unroll
        for (int j = tid; j < BM*8; j += 512){
            int row = j >> 3, ch = j & 7;
            cp16(stg + row*144 + ch*16, baseA + (long)row*p.lda + ch*8);
        }
        const fp16* baseB = p.Bf + boff + bT[tap] + k0;
        #pragma unroll
        for (int j = tid; j < 1024; j += 512){
            int row = j >> 3, ch = j & 7;
            cp16(stg + TA + row*144 + ch*16, baseB + (long)row*p.ldb + ch*8);
        }
    };

    loadChunk(0); cp_commit();
    if (nch > 1){ loadChunk(1); cp_commit(); }

    for (int c=0; c<nch; c++){
        if (c+2 < nch){ loadChunk(c+2); cp_commit(); cp_wait2(); }
        else if (c+1 < nch){ cp_wait1(); }
        else { cp_wait0(); }
        __syncthreads();

        uint32_t stg = smb + (c % 3)*STG;
        uint32_t aB_ = stg, bB = stg + TA;

        int lr = lane & 15, lcs = lane >> 4;
        int gb = lane >> 3, bnr = lane & 7;
        int rowA = wm*(MT*16) + lr;
        int rowB = wn*32 + ((gb >> 1) << 3) + bnr;

        #pragma unroll
        for (int ks=0; ks<4; ks++){
            uint32_t af[MT][4], bf[4][2];
            uint32_t aoffb = (uint32_t)((rowA*9 + ks*2 + lcs) * 16);
            #pragma unroll
            for (int mt=0; mt<MT; mt++)
                ldsm_x4(af[mt], aB_ + aoffb + mt*2304);
            uint32_t boffb = (uint32_t)((rowB*9 + ks*2 + (gb & 1)) * 16);
            uint32_t t4[4];
            #pragma unroll
            for (int np=0; np<2; np++){
                ldsm_x4(t4, bB + boffb + np*2304);
                bf[np*2][0]=t4[0]; bf[np*2][1]=t4[1]; bf[np*2+1][0]=t4[2]; bf[np*2+1][1]=t4[3];
            }
            #pragma unroll
            for (int mt=0; mt<MT; mt++)
                #pragma unroll
                for (int nt=0; nt<4; nt++)
                    mma16816(acc[mt][nt], af[mt], bf[nt]);
        }
        __syncthreads();
    }

    float* eps = (float*)sm;
    #pragma unroll
    for (int mt=0; mt<MT; mt++){
        int r0 = wm*(MT*16) + mt*16 + (lane >> 2);
        #pragma unroll
        for (int nt=0; nt<4; nt++){
            int c0 = wn*32 + nt*8 + (lane & 3)*2;
            eps[r0*132 + c0]       = acc[mt][nt][0];
            eps[r0*132 + c0 + 1]   = acc[mt][nt][1];
            eps[(r0+8)*132 + c0]   = acc[mt][nt][2];
            eps[(r0+8)*132 + c0+1] = acc[mt][nt][3];
        }
    }
    __syncthreads();

    const float* bias = p.bias ? (p.bias + (long)blockIdx.z*p.biasZ) : (const float*)0;
    long czo = (long)blockIdx.z * p.cZ;
    long ozo = (long)blockIdx.z * p.oZ;
    for (int j = tid; j < BM*128; j += 512){
        int rr = j >> 7, cc = j & 127;
        long m = m0 + rr;
        int n = n0 + cc;
        float val = eps[rr*132 + cc];
        if (bias) val += bias[n];
        if (p.epi & 2){ val = val / (1.f + expf(-val)); }
        if (p.epi & 4){ val += p.add[m*p.ldadd + n]; }
        if (p.Cf && n >= p.cfMin) p.Cf[m*p.ldc + czo + n] = val;
        if (n < p.splitNmax)
            p.Oh[m*p.ldo + ozo + n] = __float2half_rn(val);
    }
}

// ---------------- gates (reads fp16 proj/v) ----------------
__global__ __launch_bounds__(256) void gates_kernel(const fp16* __restrict__ pjf,
        const fp16* __restrict__ vbf, const float* __restrict__ wif,
        const float* __restrict__ bif, float* __restrict__ gates){
    __shared__ float As[16*128];
    __shared__ float Ws[128*17];
    int m0 = blockIdx.x*16;
    int tid = threadIdx.x;
    int r = tid >> 4, g = tid & 15;
    float acc = 0.f;
    for (int j0=0; j0<6144; j0+=128){
        __syncthreads();
        for (int e=tid; e<2048; e+=256){
            int jj = e & 127, rr = e >> 7;
            int j = j0 + jj;
            int hh = j/768, t = j - hh*768;
            long m = m0 + rr;
            fp16 v = (t < 512) ? pjf[m*4096 + hh*512 + t]
                               : vbf[m*2048 + hh*256 + (t-512)];
            As[rr*128 + jj] = __half2float(v);
        }
        for (int e=tid; e<2048; e+=256){
            int jj = e & 127, gg = e >> 7;
            Ws[jj*17 + gg] = wif[(long)gg*6144 + j0 + jj];
        }
        __syncthreads();
        #pragma unroll 8
        for (int j=0;j<128;j++) acc += As[r*128 + j]*Ws[j*17 + g];
    }
    gates[(long)(m0+r)*16 + g] = acc + bif[g];
}

// ---------------- per-(b,h) scans ----------------
__global__ __launch_bounds__(512) void scan_kernel(const float* __restrict__ gates,
        float* __restrict__ ga, float* __restrict__ Ma, float* __restrict__ ea){
    int bh = blockIdx.x, b = bh >> 3, h = bh & 7;
    int t = threadIdx.x;
    __shared__ float sd[512];
    long base = (long)b*Lq;
    float ls[3], fc[3];
    #pragma unroll
    for (int u=0;u<3;u++){
        int l = t*3 + u;
        float f = gates[(base + l)*16 + 8 + h];
        ls[u] = (f >= 0.f) ? -log1pf(expf(-f)) : (f - log1pf(expf(f)));
    }
    float tot = ls[0] + ls[1] + ls[2];
    sd[t] = tot;
    __syncthreads();
    for (int off=1; off<512; off<<=1){
        float add = (t >= off) ? sd[t-off] : 0.f;
        __syncthreads();
        sd[t] += add;
        __syncthreads();
    }
    float excl = (t > 0) ? sd[t-1] : 0.f;
    fc[0] = excl + ls[0]; fc[1] = fc[0] + ls[1]; fc[2] = fc[1] + ls[2];
    __syncthreads();
    float gv[3], pm[3];
    #pragma unroll
    for (int u=0;u<3;u++){
        int l = t*3 + u;
        float ig = gates[(base + l)*16 + h];
        gv[u] = expf(ig) - fc[u];
    }
    pm[0] = gv[0]; pm[1] = fmaxf(pm[0], gv[1]); pm[2] = fmaxf(pm[1], gv[2]);
    sd[t] = pm[2];
    __syncthreads();
    for (int off=1; off<512; off<<=1){
        float add = (t >= off) ? sd[t-off] : -3.4e38f;
        __syncthreads();
        sd[t] = fmaxf(sd[t], add);
        __syncthreads();
    }
    float exm = (t > 0) ? sd[t-1] : -3.4e38f;
    #pragma unroll
    for (int u=0;u<3;u++){
        int l = t*3 + u;
        float Ml = fmaxf(exm, pm[u]);
        ga[(long)bh*Lq + l] = gv[u];
        Ma[(long)bh*Lq + l] = Ml;
        ea[(long)bh*Lq + l] = expf(-fc[u] - Ml);
    }
}

// ---------------- tensor-core mLSTM attention + fused epilogue ----------------
#define Q_OFF  0
#define KB_OFF 33792
#define VB_OFF 52224
#define E_OFF  70656
#define ATT_SMEM 70912

__global__ __launch_bounds__(128, 1) void attn2(
    const fp16* __restrict__ pjf, const fp16* __restrict__ vbf,
    const float* __restrict__ qk, const float* __restrict__ y,
    const float* __restrict__ ga, const float* __restrict__ Ma,
    const float* __restrict__ ea, const float* __restrict__ skip,
    const float* __restrict__ hnw,
    fp16* __restrict__ xmf)
{
    extern __shared__ char sm[];
    const uint32_t smb = smem_u32(sm);
    float* Esm = (float*)(sm + E_OFF);

    int tid = threadIdx.x, w = tid >> 5, lane = tid & 31;
    int bh = blockIdx.y, b = bh >> 3, h = bh & 7;
    int qt = (int)gridDim.x - 1 - (int)blockIdx.x;
    long mbase = (long)b*Lq;
    int o0 = qt*64;

    int rowg = w*16 + (lane >> 2);
    float F0  = expf(-Ma[(long)bh*Lq + o0 + rowg])     * 0.0625f;
    float F8  = expf(-Ma[(long)bh*Lq + o0 + rowg + 8]) * 0.0625f;
    float en0 = ea[(long)bh*Lq + o0 + rowg];
    float en8 = ea[(long)bh*Lq + o0 + rowg + 8];

    for (int j = tid; j < 2048; j += 128){
        int row = j >> 5, c = j & 31;
        cp16(smb + Q_OFF + row*528 + c*16, pjf + (mbase + o0 + row)*4096 + h*512 + c*8);
    }
    cp_commit();

    int total = (qt + 1)*8;
    auto issueItem = [&](int idx){
        int it = idx >> 3, sub = idx & 7;
        long i0 = (long)it*64;
        uint32_t buf; const fp16* src0; long ldg, goff;
        if (sub < 4){ buf = smb + KB_OFF + (sub & 1)*9216; src0 = pjf; ldg = 4096; goff = h*512 + 256 + sub*64; }
        else        { buf = smb + VB_OFF + (sub & 1)*9216; src0 = vbf; ldg = 2048; goff = h*256 + (sub - 4)*64; }
        for (int j = tid; j < 512; j += 128){
            int row = j >> 3, c8 = j & 7;
            cp16(buf + row*144 + c8*16, src0 + (mbase + i0 + row)*ldg + goff + c8*8);
        }
    };
    issueItem(0); cp_commit();
    if (total > 1) issueItem(1);
    cp_commit();

    float accH[32][4];
    #pragma unroll
    for (int g=0; g<32; g++){ accH[g][0]=0.f; accH[g][1]=0.f; accH[g][2]=0.f; accH[g][3]=0.f; }
    float sacc[8][4];
    uint32_t pk[8][2];
    float rs0 = 0.f, rs1 = 0.f;

    uint32_t qrow = (uint32_t)((w*16 + (lane & 15))*528 + (lane >> 4)*16);
    int gb = lane >> 3;
    uint32_t krow = (uint32_t)(((((gb >> 1) << 3) + (lane & 7)))*144 + (gb & 1)*16);
    uint32_t vrow = (uint32_t)((lane & 15)*144 + (lane >> 4)*16);

    for (int idx = 0; idx < total; idx++){
        int it = idx >> 3, sub = idx & 7;
        cp_wait1();
        __syncthreads();
        if (sub < 4){
            if (sub == 0){
                if (tid < 64) Esm[tid] = expf(ga[(long)bh*Lq + (long)it*64 + tid]);
                #pragma unroll
                for (int g=0; g<8; g++){ sacc[g][0]=0.f; sacc[g][1]=0.f; sacc[g][2]=0.f; sacc[g][3]=0.f; }
            }
            uint32_t kb = smb + KB_OFF + (sub & 1)*9216;
            #pragma unroll
            for (int ks=0; ks<4; ks++){
                uint32_t q4[4];
                ldsm_x4(q4, smb + Q_OFF + qrow + sub*128 + ks*32);
                #pragma unroll
                for (int kt=0; kt<4; kt++){
                    uint32_t b4[4];
                    ldsm_x4(b4, kb + krow + kt*(16*144) + ks*32);
                    mma16816(sacc[kt*2],   q4, b4);
                    mma16816(sacc[kt*2+1], q4, b4 + 2);
                }
            }
            if (sub == 3){
                bool diag = (it == qt);
                #pragma unroll
                for (int nt=0; nt<8; nt++){
                    int cb = nt*8 + (lane & 3)*2;
                    float e0 = Esm[cb], e1 = Esm[cb+1];
                    float w00 = e0*F0, w01 = e1*F0, w10 = e0*F8, w11 = e1*F8;
                    if (diag){
                        if (cb     > rowg)     w00 = 0.f;
                        if (cb + 1 > rowg)     w01 = 0.f;
                        if (cb     > rowg + 8) w10 = 0.f;
                        if (cb + 1 > rowg + 8) w11 = 0.f;
                    }
                    float c0 = sacc[nt][0]*w00, c1 = sacc[nt][1]*w01;
                    float c2 = sacc[nt][2]*w10, c3 = sacc[nt][3]*w11;
                    rs0 += c0 + c1; rs1 += c2 + c3;
                    pk[nt][0] = pack2(__float2half_rn(c0), __float2half_rn(c1));
                    pk[nt][1] = pack2(__float2half_rn(c2), __float2half_rn(c3));
                }
            }
        } else {
            int vc = sub - 4;
            uint32_t vbb = smb + VB_OFF + (sub & 1)*9216;
            #pragma unroll
            for (int kk=0; kk<4; kk++){
                uint32_t aP[4] = { pk[2*kk][0], pk[2*kk][1], pk[2*kk+1][0], pk[2*kk+1][1] };
                #pragma unroll
                for (int np=0; np<4; np++){
                    uint32_t tH[4];
                    ldsm_x4t(tH, vbb + vrow + kk*(16*144) + np*32);
                    int g0 = vc*8 + 2*np;
                    mma16816(accH[g0],   aP, tH);
                    mma16816(accH[g0+1], aP, tH + 2);
                }
            }
        }
        __syncthreads();
        if (idx + 2 < total) issueItem(idx + 2);
        cp_commit();
    }

    rs0 += __shfl_xor_sync(0xffffffffu, rs0, 1);
    rs0 += __shfl_xor_sync(0xffffffffu, rs0, 2);
    rs1 += __shfl_xor_sync(0xffffffffu, rs1, 1);
    rs1 += __shfl_xor_sync(0xffffffffu, rs1, 2);
    float inv0 = 1.f / fmaxf(fabsf(rs0), en0);
    float inv1 = 1.f / fmaxf(fabsf(rs1), en8);

    float s0=0.f, q0=0.f, s1=0.f, q1=0.f;
    #pragma unroll
    for (int g=0; g<32; g++){
        float v0 = accH[g][0]*inv0, v1 = accH[g][1]*inv0;
        float v2 = accH[g][2]*inv1, v3 = accH[g][3]*inv1;
        accH[g][0]=v0; accH[g][1]=v1; accH[g][2]=v2; accH[g][3]=v3;
        s0 += v0 + v1; q0 += v0*v0 + v1*v1;
        s1 += v2 + v3; q1 += v2*v2 + v3*v3;
    }
    s0 += __shfl_xor_sync(0xffffffffu, s0, 1); s0 += __shfl_xor_sync(0xffffffffu, s0, 2);
    q0 += __shfl_xor_sync(0xffffffffu, q0, 1); q0 += __shfl_xor_sync(0xffffffffu, q0, 2);
    s1 += __shfl_xor_sync(0xffffffffu, s1, 1); s1 += __shfl_xor_sync(0xffffffffu, s1, 2);
    q1 += __shfl_xor_sync(0xffffffffu, q1, 1); q1 += __shfl_xor_sync(0xffffffffu, q1, 2);
    float mu0 = s0*(1.f/256.f), var0 = q0*(1.f/256.f) - mu0*mu0, rst0 = rsqrtf(var0 + 1e-5f);
    float mu1 = s1*(1.f/256.f), var1 = q1*(1.f/256.f) - mu1*mu1, rst1 = rsqrtf(var1 + 1e-5f);

    long mr0 = mbase + o0 + rowg;
    long mr8 = mr0 + 8;
    #pragma unroll
    for (int g=0; g<32; g++){
        int d0 = g*8 + (lane & 3)*2;
        int col = h*256 + d0;
        float2 hw = *(const float2*)(hnw + d0);
        float2 sk = *(const float2*)(skip + col);
        {
            float2 q2 = *(const float2*)(qk + mr0*2048 + col);
            float2 x2 = *(const float2*)(y + mr0*4096 + 2048 + col);
            float hv0 = (accH[g][0] - mu0)*rst0*hw.x;
            float hv1 = (accH[g][1] - mu0)*rst0*hw.y;
            float a0 = hv0 + sk.x*q2.x, a1 = hv1 + sk.y*q2.y;
            float r0 = a0 * (x2.x / (1.f + expf(-x2.x)));
            float r1 = a1 * (x2.y / (1.f + expf(-x2.y)));
            *(uint32_t*)(xmf + mr0*2048 + col) = pack2(__float2half_rn(r0), __float2half_rn(r1));
        }
        {
            float2 q2 = *(const float2*)(qk + mr8*2048 + col);
            float2 x2 = *(const float2*)(y + mr8*4096 + 2048 + col);
            float hv0 = (accH[g][2] - mu1)*rst1*hw.x;
            float hv1 = (accH[g][3] - mu1)*rst1*hw.y;
            float a0 = hv0 + sk.x*q2.x, a1 = hv1 + sk.y*q2.y;
            float r0 = a0 * (x2.x / (1.f + expf(-x2.x)));
            float r1 = a1 * (x2.y / (1.f + expf(-x2.y)));
            *(uint32_t*)(xmf + mr8*2048 + col) = pack2(__float2half_rn(r0), __float2half_rn(r1));
        }
    }
}

// ---------------- host ----------------
extern "C" void kernel_launch(void* const* d_in, const int* in_sizes, int n_in,
                              void* d_out, int out_size){
    const float* x      = (const float*)d_in[0];
    const float* ln_w   = (const float*)d_in[1];
    const float* ln_b   = (const float*)d_in[2];
    const float* w1     = (const float*)d_in[3];
    const float* b1     = (const float*)d_in[4];
    const float* conv_w = (const float*)d_in[5];
    const float* conv_b = (const float*)d_in[6];
    const float* skip   = (const float*)d_in[7];
    const float* wqk    = (const float*)d_in[8];
    const float* bqk    = (const float*)d_in[9];
    const float* wv     = (const float*)d_in[10];
    const float* bv     = (const float*)d_in[11];
    const float* wif    = (const float*)d_in[12];
    const float* bif    = (const float*)d_in[13];
    const float* hn_w   = (const float*)d_in[14];
    const float* w2     = (const float*)d_in[15];
    const float* b2     = (const float*)d_in[16];
    float* out = (float*)d_out;

    fp16 *xlnf,*x1f,*qkf,*xmf,*pjf,*vbf;
    fp16 *w1f,*cwtf,*wqkTf,*wvTf,*w2f;
    float *y,*qkb,*gates,*gA,*MA,*eA;
    cudaGetSymbolAddress((void**)&xlnf, d_xlnf);
    cudaGetSymbolAddress((void**)&y,    d_y);
    cudaGetSymbolAddress((void**)&x1f,  d_x1f);
    cudaGetSymbolAddress((void**)&qkb,  d_qk);
    cudaGetSymbolAddress((void**)&qkf,  d_qkf);
    cudaGetSymbolAddress((void**)&pjf,  d_pjf);
    cudaGetSymbolAddress((void**)&vbf,  d_vbf);
    cudaGetSymbolAddress((void**)&xmf,  d_xmf);
    cudaGetSymbolAddress((void**)&gates,d_gates);
    cudaGetSymbolAddress((void**)&gA,   d_g);
    cudaGetSymbolAddress((void**)&MA,   d_M);
    cudaGetSymbolAddress((void**)&eA,   d_enm);
    cudaGetSymbolAddress((void**)&w1f,  d_w1f);
    cudaGetSymbolAddress((void**)&cwtf, d_cwtf);
    cudaGetSymbolAddress((void**)&wqkTf,d_wqkTf);
    cudaGetSymbolAddress((void**)&wvTf, d_wvTf);
    cudaGetSymbolAddress((void**)&w2f,  d_w2f);

    cudaFuncSetAttribute(hgemm<2>, cudaFuncAttributeMaxDynamicSharedMemorySize, 110592);
    cudaFuncSetAttribute(hgemm<1>, cudaFuncAttributeMaxDynamicSharedMemorySize, 82944);
    cudaFuncSetAttribute(attn2, cudaFuncAttributeMaxDynamicSharedMemorySize, ATT_SMEM);

    // order chosen so ncu's captured slot (4th launch) hits hgemm<2> GEMM1
    quant_plain4<<<(int)((4096L*1024/4 + 255)/256), 256>>>((const float4*)w1, (__half2*)w1f, 4096L*1024/4);  // 1
    ln_kernel<<<Mq, 256>>>(x, ln_w, ln_b, xlnf);                                                             // 2
    quant_plain4<<<(int)((1024L*2048/4 + 255)/256), 256>>>((const float4*)w2, (__half2*)w2f, 1024L*2048/4);  // 3

    // 4: y = LN(x) @ w1^T + b1 : f32 y only for x2 half (cfMin=2048) + fp16 x1 (cols < 2048)
    {
        G5P p = {};
        p.Af = xlnf; p.Bf = w1f;
        p.Cf = y; p.Oh = x1f; p.bias = b1;
        p.K = 1024; p.lda = 1024; p.ldb = 1024; p.ldc = 4096; p.ldo = 2048;
        p.epi = 1; p.ntaps = 1; p.splitNmax = 2048; p.cfMin = 2048;
        hgemm<2><<<dim3(32, 24, 1), 512, 110592>>>(p);
    }

    prep_cwt<<<(int)(((long)Cq*Cq/2 + 255)/256), 256>>>((const float4*)conv_w, (__half2*)cwtf);
    prep_wqkv<<<(Hq*512*256 + Hq*256*256 + 255)/256, 256>>>(wqk, wv, wqkTf, wvTf);

    // qk = silu(conv(x1)) — single launch, batch-dependent taps (conv over batch axis)
    {
        G5P p = {};
        p.Af = x1f; p.Bf = cwtf;
        p.Cf = qkb; p.Oh = qkf; p.bias = conv_b;
        p.K = Cq; p.lda = Cq; p.ldb = Cq; p.ldc = Cq; p.ldo = Cq;
        p.epi = 1|2|8; p.splitNmax = Cq; p.cfMin = 0;
        p.ntaps  = 1; p.aTap[0]  = 0;              p.bTap[0]  = (long)3*Cq*Cq;
        p.ntaps2 = 2; p.aTap2[0] = 0;              p.bTap2[0] = (long)2*Cq*Cq;
                      p.aTap2[1] = (long)Lq*Cq;    p.bTap2[1] = (long)3*Cq*Cq;
        hgemm<2><<<dim3(16, 24, 1), 512, 110592>>>(p);
    }

    // per-head proj = qk_h @ wqk_h + bqk  (fp16 only; gates reads fp16)
    {
        G5P p = {};
        p.Af = qkf; p.Bf = wqkTf;
        p.Cf = 0; p.Oh = pjf; p.bias = bqk;
        p.K = 256; p.lda = 2048; p.ldb = 256; p.ldo = 4096;
        p.aZ = 256; p.bZ = (long)512*256; p.biasZ = 512; p.oZ = 512;
        p.epi = 1; p.ntaps = 1; p.splitNmax = 512;
        hgemm<2><<<dim3(4, 24, Hq), 512, 110592>>>(p);
    }
    // per-head v = x1_h @ wv_h + bv  (fp16 only)
    {
        G5P p = {};
        p.Af = x1f; p.Bf = wvTf;
        p.Cf = 0; p.Oh = vbf; p.bias = bv;
        p.K = 256; p.lda = 2048; p.ldb = 256; p.ldo = 2048;
        p.aZ = 256; p.bZ = (long)256*256; p.biasZ = 256; p.oZ = 256;
        p.epi = 1; p.ntaps = 1; p.splitNmax = 256;
        hgemm<2><<<dim3(2, 24, Hq), 512, 110592>>>(p);
    }

    gates_kernel<<<Mq/16, 256>>>(pjf, vbf, wif, bif, gates);
    scan_kernel<<<Bq*Hq, 512>>>(gates, gA, MA, eA);

    attn2<<<dim3(24, 16), 128, ATT_SMEM>>>(pjf, vbf, qkb, y,
                                           gA, MA, eA, skip, hn_w, xmf);

    // out = xm @ w2^T + b2 + x  (BM=64 tiles → 384 blocks)
    {
        G5P p = {};
        p.Af = xmf; p.Bf = w2f;
        p.Cf = out; p.bias = b2; p.add = x;
        p.K = Cq; p.lda = 2048; p.ldb = 2048; p.ldc = 1024; p.ldadd = 1024;
        p.epi = 1|4; p.ntaps = 1; p.splitNmax = 0; p.cfMin = 0;
        hgemm<1><<<dim3(8, 48, 1), 512, 82944>>>(p);
    }
}

// round 11
// speedup vs baseline: 1.6602x; 1.0834x over previous
#include <cuda_runtime.h>
#include <cuda_fp16.h>
#include <math.h>
#include <stdint.h>

#define Bq 2
#define Lq 1536
#define Dq 1024
#define Hq 8
#define Cq 2048
#define DPHq 256
#define Mq (Bq*Lq)   /* 3072 */

typedef __half fp16;

// ---------------- scratch (static device globals; no allocation) ----------------
__device__ __align__(128) fp16  d_xlnf[(size_t)Mq*Dq];
__device__ __align__(128) float d_y[(size_t)Mq*4096];
__device__ __align__(128) fp16  d_x1f[(size_t)Mq*Cq];
__device__ __align__(128) float d_qk[(size_t)Mq*Cq];
__device__ __align__(128) fp16  d_qkf[(size_t)Mq*Cq];
__device__ __align__(128) fp16  d_pjf[(size_t)Mq*4096];
__device__ __align__(128) fp16  d_vbf[(size_t)Mq*Cq];
__device__ __align__(128) fp16  d_xmf[(size_t)Mq*Cq];
__device__ float d_gates[(size_t)Mq*16];
__device__ float d_g[16*Lq];
__device__ float d_M[16*Lq];
__device__ float d_enm[16*Lq];
__device__ __align__(128) fp16  d_w1f[4096*1024];
__device__ __align__(128) fp16  d_cwtf[(size_t)4*Cq*Cq];
__device__ __align__(128) fp16  d_wqkTf[Hq*512*256];
__device__ __align__(128) fp16  d_wvTf[Hq*256*256];
__device__ __align__(128) fp16  d_w2f[1024*2048];

// ---------------- helpers ----------------
__device__ __forceinline__ uint32_t smem_u32(const void* p){
    return (uint32_t)__cvta_generic_to_shared(p);
}
__device__ __forceinline__ void cp16(uint32_t dst, const void* src){
    asm volatile("cp.async.cg.shared.global [%0], [%1], 16;" :: "r"(dst), "l"(src));
}
__device__ __forceinline__ void cp_commit(){ asm volatile("cp.async.commit_group;" ::: "memory"); }
__device__ __forceinline__ void cp_wait0(){ asm volatile("cp.async.wait_group 0;" ::: "memory"); }
__device__ __forceinline__ void cp_wait1(){ asm volatile("cp.async.wait_group 1;" ::: "memory"); }
__device__ __forceinline__ void cp_wait2(){ asm volatile("cp.async.wait_group 2;" ::: "memory"); }

__device__ __forceinline__ void ldsm_x4(uint32_t* r, uint32_t addr){
    asm volatile("ldmatrix.sync.aligned.m8n8.x4.shared.b16 {%0,%1,%2,%3}, [%4];"
                 : "=r"(r[0]), "=r"(r[1]), "=r"(r[2]), "=r"(r[3]) : "r"(addr));
}
__device__ __forceinline__ void ldsm_x4t(uint32_t* r, uint32_t addr){
    asm volatile("ldmatrix.sync.aligned.m8n8.x4.trans.shared.b16 {%0,%1,%2,%3}, [%4];"
                 : "=r"(r[0]), "=r"(r[1]), "=r"(r[2]), "=r"(r[3]) : "r"(addr));
}
__device__ __forceinline__ void mma16816(float* d, const uint32_t* a, const uint32_t* b){
    asm volatile(
        "mma.sync.aligned.m16n8k16.row.col.f32.f16.f16.f32 "
        "{%0,%1,%2,%3}, {%4,%5,%6,%7}, {%8,%9}, {%0,%1,%2,%3};"
        : "+f"(d[0]), "+f"(d[1]), "+f"(d[2]), "+f"(d[3])
        : "r"(a[0]), "r"(a[1]), "r"(a[2]), "r"(a[3]), "r"(b[0]), "r"(b[1]));
}
__device__ __forceinline__ uint32_t pack2(fp16 a, fp16 b){
    uint16_t ua = *(uint16_t*)&a, ub = *(uint16_t*)&b;
    return (uint32_t)ua | ((uint32_t)ub << 16);
}

// ---------------- prep kernels (coalesced) ----------------
__global__ void quant_plain4(const float4* __restrict__ w, __half2* __restrict__ f, long n4){
    long i = (long)blockIdx.x*256 + threadIdx.x;
    if (i >= n4) return;
    float4 v = w[i];
    f[2*i]   = __floats2half2_rn(v.x, v.y);
    f[2*i+1] = __floats2half2_rn(v.z, v.w);
}
__global__ void prep_cwt(const float4* __restrict__ cw, __half2* __restrict__ f2){
    const long NP = (long)Cq*Cq/2;
    long i = (long)blockIdx.x*256 + threadIdx.x;
    if (i >= NP) return;
    float4 a = cw[2*i], b = cw[2*i+1];
    f2[i]        = __floats2half2_rn(a.x, b.x);
    f2[NP + i]   = __floats2half2_rn(a.y, b.y);
    f2[2*NP + i] = __floats2half2_rn(a.z, b.z);
    f2[3*NP + i] = __floats2half2_rn(a.w, b.w);
}
__global__ void prep_wqkv(const float* __restrict__ wqk, const float* __restrict__ wv,
                          fp16* __restrict__ qf, fp16* __restrict__ vf){
    int idx = blockIdx.x*256 + threadIdx.x;
    if (idx < Hq*512*256){
        int hh = idx/(512*256); int r = idx%(512*256); int o = r/256; int i = r%256;
        qf[idx] = __float2half_rn(wqk[hh*131072 + i*512 + o]);
    } else {
        int j = idx - Hq*512*256;
        if (j < Hq*256*256){
            int hh = j/65536; int r = j%65536; int o = r/256; int i = r%256;
            vf[j] = __float2half_rn(wv[hh*65536 + i*256 + o]);
        }
    }
}

// ---------------- LayerNorm on x -> fp16 ----------------
__global__ __launch_bounds__(256) void ln_kernel(const float* __restrict__ x,
        const float* __restrict__ w, const float* __restrict__ bb,
        fp16* __restrict__ of){
    int m = blockIdx.x, t = threadIdx.x;
    __shared__ float s1[256], s2[256];
    float v[4]; float s = 0.f, q = 0.f;
    #pragma unroll
    for (int u=0;u<4;u++){ v[u] = x[(long)m*Dq + t + u*256]; s += v[u]; q += v[u]*v[u]; }
    s1[t] = s; s2[t] = q; __syncthreads();
    for (int off=128; off; off>>=1){
        if (t < off){ s1[t] += s1[t+off]; s2[t] += s2[t+off]; }
        __syncthreads();
    }
    float mu = s1[0]*(1.f/1024.f);
    float var = s2[0]*(1.f/1024.f) - mu*mu;
    float rs = rsqrtf(var + 1e-5f);
    #pragma unroll
    for (int u=0;u<4;u++){
        int c = t + u*256;
        of[(long)m*Dq + c] = __float2half_rn((v[u]-mu)*rs*w[c] + bb[c]);
    }
}

// ---------------- fp16 mma.sync GEMM (512 threads, BK=64): C = A @ B^T ----------------
// epi bits: 1=bias, 2=silu, 4=residual add, 8=conv mode (batch taps + heavy-first y)
struct G5P {
    const fp16 *Af, *Bf;
    float* Cf;
    fp16 *Oh;
    const float* bias; const float* add;
    int K, lda, ldb, ldc, ldo, ldadd, epi, ntaps, ntaps2, splitNmax, cfMin;
    long aZ, bZ, cZ, biasZ, oZ;
    long aTap[2], bTap[2];
    long aTap2[2], bTap2[2];
};

template<int MT>
__global__ __launch_bounds__(512, 1) void hgemm(G5P p){
    constexpr int BM = MT*64;
    constexpr int TA = BM*144;
    constexpr int TB = 128*144;
    constexpr int STG = TA + TB;
    extern __shared__ char sm[];
    int tid = threadIdx.x;
    int warp = tid >> 5, lane = tid & 31;
    int wm = warp >> 2, wn = warp & 3;

    // conv mode: heavy blocks (batch 1, 2 taps) first
    long byy = (p.epi & 8) ? (long)(gridDim.y - 1 - blockIdx.y) : (long)blockIdx.y;
    long m0 = byy*BM;
    int  n0 = blockIdx.x*128;

    long arow; int ntaps; long aT[2], bT[2];
    if (p.epi & 8){
        int batch = (int)(m0 / Lq);
        arow = m0 - (long)batch*Lq;
        if (batch == 0){ ntaps = p.ntaps;  aT[0]=p.aTap[0];  bT[0]=p.bTap[0];  aT[1]=p.aTap[1];  bT[1]=p.bTap[1]; }
        else           { ntaps = p.ntaps2; aT[0]=p.aTap2[0]; bT[0]=p.bTap2[0]; aT[1]=p.aTap2[1]; bT[1]=p.bTap2[1]; }
    } else {
        arow = m0; ntaps = p.ntaps;
        aT[0]=p.aTap[0]; bT[0]=p.bTap[0]; aT[1]=p.aTap[1]; bT[1]=p.bTap[1];
    }

    long aoff = (long)blockIdx.z*p.aZ + arow*p.lda;
    long boff = (long)blockIdx.z*p.bZ + (long)n0*p.ldb;
    int cpt = p.K >> 6;
    int nch = ntaps * cpt;

    uint32_t smb = smem_u32(sm);
    float acc[MT][4][4] = {};

    auto loadChunk = [&](int c){
        int tap = c / cpt;
        int k0  = (c - tap*cpt) << 6;
        uint32_t stg = smb + (c % 3)*STG;
        const fp16* baseA = p.Af + aoff + aT[tap] + k0;
        #pragma unroll
        for (int j = tid; j < BM*8; j += 512){
            int row = j >> 3, ch = j & 7;
            cp16(stg + row*144 + ch*16, baseA + (long)row*p.lda + ch*8);
        }
        const fp16* baseB = p.Bf + boff + bT[tap] + k0;
        #pragma unroll
        for (int j = tid; j < 1024; j += 512){
            int row = j >> 3, ch = j & 7;
            cp16(stg + TA + row*144 + ch*16, baseB + (long)row*p.ldb + ch*8);
        }
    };

    loadChunk(0); cp_commit();
    if (nch > 1){ loadChunk(1); cp_commit(); }

    for (int c=0; c<nch; c++){
        if (c+2 < nch){ loadChunk(c+2); cp_commit(); cp_wait2(); }
        else if (c+1 < nch){ cp_wait1(); }
        else { cp_wait0(); }
        __syncthreads();

        uint32_t stg = smb + (c % 3)*STG;
        uint32_t aB_ = stg, bB = stg + TA;

        int lr = lane & 15, lcs = lane >> 4;
        int gb = lane >> 3, bnr = lane & 7;
        int rowA = wm*(MT*16) + lr;
        int rowB = wn*32 + ((gb >> 1) << 3) + bnr;

        #pragma unroll
        for (int ks=0; ks<4; ks++){
            uint32_t af[MT][4], bf[4][2];
            uint32_t aoffb = (uint32_t)((rowA*9 + ks*2 + lcs) * 16);
            #pragma unroll
            for (int mt=0; mt<MT; mt++)
                ldsm_x4(af[mt], aB_ + aoffb + mt*2304);
            uint32_t boffb = (uint32_t)((rowB*9 + ks*2 + (gb & 1)) * 16);
            uint32_t t4[4];
            #pragma unroll
            for (int np=0; np<2; np++){
                ldsm_x4(t4, bB + boffb + np*2304);
                bf[np*2][0]=t4[0]; bf[np*2][1]=t4[1]; bf[np*2+1][0]=t4[2]; bf[np*2+1][1]=t4[3];
            }
            #pragma unroll
            for (int mt=0; mt<MT; mt++)
                #pragma unroll
                for (int nt=0; nt<4; nt++)
                    mma16816(acc[mt][nt], af[mt], bf[nt]);
        }
        __syncthreads();
    }

    float* eps = (float*)sm;
    #pragma unroll
    for (int mt=0; mt<MT; mt++){
        int r0 = wm*(MT*16) + mt*16 + (lane >> 2);
        #pragma unroll
        for (int nt=0; nt<4; nt++){
            int c0 = wn*32 + nt*8 + (lane & 3)*2;
            eps[r0*132 + c0]       = acc[mt][nt][0];
            eps[r0*132 + c0 + 1]   = acc[mt][nt][1];
            eps[(r0+8)*132 + c0]   = acc[mt][nt][2];
            eps[(r0+8)*132 + c0+1] = acc[mt][nt][3];
        }
    }
    __syncthreads();

    const float* bias = p.bias ? (p.bias + (long)blockIdx.z*p.biasZ) : (const float*)0;
    long czo = (long)blockIdx.z * p.cZ;
    long ozo = (long)blockIdx.z * p.oZ;
    for (int j = tid; j < BM*128; j += 512){
        int rr = j >> 7, cc = j & 127;
        long m = m0 + rr;
        int n = n0 + cc;
        float val = eps[rr*132 + cc];
        if (bias) val += bias[n];
        if (p.epi & 2){ val = val / (1.f + expf(-val)); }
        if (p.epi & 4){ val += p.add[m*p.ldadd + n]; }
        if (p.Cf && n >= p.cfMin) p.Cf[m*p.ldc + czo + n] = val;
        if (n < p.splitNmax)
            p.Oh[m*p.ldo + ozo + n] = __float2half_rn(val);
    }
}

// ---------------- gates (reads fp16 proj/v) ----------------
__global__ __launch_bounds__(256) void gates_kernel(const fp16* __restrict__ pjf,
        const fp16* __restrict__ vbf, const float* __restrict__ wif,
        const float* __restrict__ bif, float* __restrict__ gates){
    __shared__ float As[16*128];
    __shared__ float Ws[128*17];
    int m0 = blockIdx.x*16;
    int tid = threadIdx.x;
    int r = tid >> 4, g = tid & 15;
    float acc = 0.f;
    for (int j0=0; j0<6144; j0+=128){
        __syncthreads();
        for (int e=tid; e<2048; e+=256){
            int jj = e & 127, rr = e >> 7;
            int j = j0 + jj;
            int hh = j/768, t = j - hh*768;
            long m = m0 + rr;
            fp16 v = (t < 512) ? pjf[m*4096 + hh*512 + t]
                               : vbf[m*2048 + hh*256 + (t-512)];
            As[rr*128 + jj] = __half2float(v);
        }
        for (int e=tid; e<2048; e+=256){
            int jj = e & 127, gg = e >> 7;
            Ws[jj*17 + gg] = wif[(long)gg*6144 + j0 + jj];
        }
        __syncthreads();
        #pragma unroll 8
        for (int j=0;j<128;j++) acc += As[r*128 + j]*Ws[j*17 + g];
    }
    gates[(long)(m0+r)*16 + g] = acc + bif[g];
}

// ---------------- per-(b,h) scans ----------------
__global__ __launch_bounds__(512) void scan_kernel(const float* __restrict__ gates,
        float* __restrict__ ga, float* __restrict__ Ma, float* __restrict__ ea){
    int bh = blockIdx.x, b = bh >> 3, h = bh & 7;
    int t = threadIdx.x;
    __shared__ float sd[512];
    long base = (long)b*Lq;
    float ls[3], fc[3];
    #pragma unroll
    for (int u=0;u<3;u++){
        int l = t*3 + u;
        float f = gates[(base + l)*16 + 8 + h];
        ls[u] = (f >= 0.f) ? -log1pf(expf(-f)) : (f - log1pf(expf(f)));
    }
    float tot = ls[0] + ls[1] + ls[2];
    sd[t] = tot;
    __syncthreads();
    for (int off=1; off<512; off<<=1){
        float add = (t >= off) ? sd[t-off] : 0.f;
        __syncthreads();
        sd[t] += add;
        __syncthreads();
    }
    float excl = (t > 0) ? sd[t-1] : 0.f;
    fc[0] = excl + ls[0]; fc[1] = fc[0] + ls[1]; fc[2] = fc[1] + ls[2];
    __syncthreads();
    float gv[3], pm[3];
    #pragma unroll
    for (int u=0;u<3;u++){
        int l = t*3 + u;
        float ig = gates[(base + l)*16 + h];
        gv[u] = expf(ig) - fc[u];
    }
    pm[0] = gv[0]; pm[1] = fmaxf(pm[0], gv[1]); pm[2] = fmaxf(pm[1], gv[2]);
    sd[t] = pm[2];
    __syncthreads();
    for (int off=1; off<512; off<<=1){
        float add = (t >= off) ? sd[t-off] : -3.4e38f;
        __syncthreads();
        sd[t] = fmaxf(sd[t], add);
        __syncthreads();
    }
    float exm = (t > 0) ? sd[t-1] : -3.4e38f;
    #pragma unroll
    for (int u=0;u<3;u++){
        int l = t*3 + u;
        float Ml = fmaxf(exm, pm[u]);
        ga[(long)bh*Lq + l] = gv[u];
        Ma[(long)bh*Lq + l] = Ml;
        ea[(long)bh*Lq + l] = expf(-fc[u] - Ml);
    }
}

// ---------------- tensor-core mLSTM attention: full-tile K/V double buffering ----------------
// smem: Q 64x528B | K0 | K1 | V0 | V1 (each 64x528B) | E[64]
#define Q_OFF  0
#define K0_OFF 33792
#define V0_OFF 101376
#define E_OFF  168960
#define ATT_SMEM 169216

__global__ __launch_bounds__(128, 1) void attn2(
    const fp16* __restrict__ pjf, const fp16* __restrict__ vbf,
    const float* __restrict__ qk, const float* __restrict__ y,
    const float* __restrict__ ga, const float* __restrict__ Ma,
    const float* __restrict__ ea, const float* __restrict__ skip,
    const float* __restrict__ hnw,
    fp16* __restrict__ xmf)
{
    extern __shared__ char sm[];
    const uint32_t smb = smem_u32(sm);
    float* Esm = (float*)(sm + E_OFF);

    int tid = threadIdx.x, w = tid >> 5, lane = tid & 31;
    int bh = blockIdx.y, b = bh >> 3, h = bh & 7;
    int qt = (int)gridDim.x - 1 - (int)blockIdx.x;
    long mbase = (long)b*Lq;
    int o0 = qt*64;

    int rowg = w*16 + (lane >> 2);
    float F0  = expf(-Ma[(long)bh*Lq + o0 + rowg])     * 0.0625f;
    float F8  = expf(-Ma[(long)bh*Lq + o0 + rowg + 8]) * 0.0625f;
    float en0 = ea[(long)bh*Lq + o0 + rowg];
    float en8 = ea[(long)bh*Lq + o0 + rowg + 8];

    // Q tile (own 64 rows, full 256 dims)
    for (int j = tid; j < 2048; j += 128){
        int row = j >> 5, c = j & 31;
        cp16(smb + Q_OFF + row*528 + c*16, pjf + (mbase + o0 + row)*4096 + h*512 + c*8);
    }
    cp_commit();

    int ntiles = qt + 1;
    auto issueTile = [&](int it){
        long i0 = (long)it*64;
        uint32_t kb = smb + K0_OFF + (it & 1)*33792;
        uint32_t vb2 = smb + V0_OFF + (it & 1)*33792;
        for (int j = tid; j < 2048; j += 128){
            int row = j >> 5, c = j & 31;
            cp16(kb + row*528 + c*16, pjf + (mbase + i0 + row)*4096 + h*512 + 256 + c*8);
        }
        for (int j = tid; j < 2048; j += 128){
            int row = j >> 5, c = j & 31;
            cp16(vb2 + row*528 + c*16, vbf + (mbase + i0 + row)*2048 + h*256 + c*8);
        }
    };
    issueTile(0); cp_commit();
    if (ntiles > 1) issueTile(1);
    cp_commit();

    float accH[32][4];
    #pragma unroll
    for (int g=0; g<32; g++){ accH[g][0]=0.f; accH[g][1]=0.f; accH[g][2]=0.f; accH[g][3]=0.f; }
    uint32_t pk[8][2];
    float rs0 = 0.f, rs1 = 0.f;

    uint32_t qrow = (uint32_t)((w*16 + (lane & 15))*528 + (lane >> 4)*16);
    int gb = lane >> 3;
    uint32_t krow = (uint32_t)(((((gb >> 1) << 3) + (lane & 7)))*528 + (gb & 1)*16);
    uint32_t vrow = (uint32_t)((lane & 15)*528 + (lane >> 4)*16);

    for (int it = 0; it < ntiles; it++){
        cp_wait1();
        if (tid < 64) Esm[tid] = expf(ga[(long)bh*Lq + (long)it*64 + tid]);
        __syncthreads();

        uint32_t kb = smb + K0_OFF + (it & 1)*33792;
        uint32_t vb2 = smb + V0_OFF + (it & 1)*33792;

        // S = Q K^T over full 256 dims
        float sacc[8][4];
        #pragma unroll
        for (int g=0; g<8; g++){ sacc[g][0]=0.f; sacc[g][1]=0.f; sacc[g][2]=0.f; sacc[g][3]=0.f; }
        #pragma unroll
        for (int ks=0; ks<16; ks++){
            uint32_t q4[4];
            ldsm_x4(q4, smb + Q_OFF + qrow + ks*32);
            #pragma unroll
            for (int kt=0; kt<4; kt++){
                uint32_t b4[4];
                ldsm_x4(b4, kb + krow + kt*(16*528) + ks*32);
                mma16816(sacc[kt*2],   q4, b4);
                mma16816(sacc[kt*2+1], q4, b4 + 2);
            }
        }
        // P = S * E[i]*F[o], causal mask on diagonal tile; repack to fp16 A-fragments
        {
            bool diag = (it == qt);
            #pragma unroll
            for (int nt=0; nt<8; nt++){
                int cb = nt*8 + (lane & 3)*2;
                float e0 = Esm[cb], e1 = Esm[cb+1];
                float w00 = e0*F0, w01 = e1*F0, w10 = e0*F8, w11 = e1*F8;
                if (diag){
                    if (cb     > rowg)     w00 = 0.f;
                    if (cb + 1 > rowg)     w01 = 0.f;
                    if (cb     > rowg + 8) w10 = 0.f;
                    if (cb + 1 > rowg + 8) w11 = 0.f;
                }
                float c0 = sacc[nt][0]*w00, c1 = sacc[nt][1]*w01;
                float c2 = sacc[nt][2]*w10, c3 = sacc[nt][3]*w11;
                rs0 += c0 + c1; rs1 += c2 + c3;
                pk[nt][0] = pack2(__float2half_rn(c0), __float2half_rn(c1));
                pk[nt][1] = pack2(__float2half_rn(c2), __float2half_rn(c3));
            }
        }
        // H += P V over full 256 dims
        #pragma unroll
        for (int kk=0; kk<4; kk++){
            uint32_t aP[4] = { pk[2*kk][0], pk[2*kk][1], pk[2*kk+1][0], pk[2*kk+1][1] };
            #pragma unroll
            for (int dc=0; dc<16; dc++){
                uint32_t tH[4];
                ldsm_x4t(tH, vb2 + vrow + kk*(16*528) + dc*32);
                mma16816(accH[2*dc],   aP, tH);
                mma16816(accH[2*dc+1], aP, tH + 2);
            }
        }
        __syncthreads();
        if (it + 2 < ntiles) issueTile(it + 2);
        cp_commit();
    }

    rs0 += __shfl_xor_sync(0xffffffffu, rs0, 1);
    rs0 += __shfl_xor_sync(0xffffffffu, rs0, 2);
    rs1 += __shfl_xor_sync(0xffffffffu, rs1, 1);
    rs1 += __shfl_xor_sync(0xffffffffu, rs1, 2);
    float inv0 = 1.f / fmaxf(fabsf(rs0), en0);
    float inv1 = 1.f / fmaxf(fabsf(rs1), en8);

    float s0=0.f, q0=0.f, s1=0.f, q1=0.f;
    #pragma unroll
    for (int g=0; g<32; g++){
        float v0 = accH[g][0]*inv0, v1 = accH[g][1]*inv0;
        float v2 = accH[g][2]*inv1, v3 = accH[g][3]*inv1;
        accH[g][0]=v0; accH[g][1]=v1; accH[g][2]=v2; accH[g][3]=v3;
        s0 += v0 + v1; q0 += v0*v0 + v1*v1;
        s1 += v2 + v3; q1 += v2*v2 + v3*v3;
    }
    s0 += __shfl_xor_sync(0xffffffffu, s0, 1); s0 += __shfl_xor_sync(0xffffffffu, s0, 2);
    q0 += __shfl_xor_sync(0xffffffffu, q0, 1); q0 += __shfl_xor_sync(0xffffffffu, q0, 2);
    s1 += __shfl_xor_sync(0xffffffffu, s1, 1); s1 += __shfl_xor_sync(0xffffffffu, s1, 2);
    q1 += __shfl_xor_sync(0xffffffffu, q1, 1); q1 += __shfl_xor_sync(0xffffffffu, q1, 2);
    float mu0 = s0*(1.f/256.f), var0 = q0*(1.f/256.f) - mu0*mu0, rst0 = rsqrtf(var0 + 1e-5f);
    float mu1 = s1*(1.f/256.f), var1 = q1*(1.f/256.f) - mu1*mu1, rst1 = rsqrtf(var1 + 1e-5f);

    long mr0 = mbase + o0 + rowg;
    long mr8 = mr0 + 8;
    #pragma unroll
    for (int g=0; g<32; g++){
        int d0 = g*8 + (lane & 3)*2;
        int col = h*256 + d0;
        float2 hw = *(const float2*)(hnw + d0);
        float2 sk = *(const float2*)(skip + col);
        {
            float2 q2 = *(const float2*)(qk + mr0*2048 + col);
            float2 x2 = *(const float2*)(y + mr0*4096 + 2048 + col);
            float hv0 = (accH[g][0] - mu0)*rst0*hw.x;
            float hv1 = (accH[g][1] - mu0)*rst0*hw.y;
            float a0 = hv0 + sk.x*q2.x, a1 = hv1 + sk.y*q2.y;
            float r0 = a0 * (x2.x / (1.f + expf(-x2.x)));
            float r1 = a1 * (x2.y / (1.f + expf(-x2.y)));
            *(uint32_t*)(xmf + mr0*2048 + col) = pack2(__float2half_rn(r0), __float2half_rn(r1));
        }
        {
            float2 q2 = *(const float2*)(qk + mr8*2048 + col);
            float2 x2 = *(const float2*)(y + mr8*4096 + 2048 + col);
            float hv0 = (accH[g][2] - mu1)*rst1*hw.x;
            float hv1 = (accH[g][3] - mu1)*rst1*hw.y;
            float a0 = hv0 + sk.x*q2.x, a1 = hv1 + sk.y*q2.y;
            float r0 = a0 * (x2.x / (1.f + expf(-x2.x)));
            float r1 = a1 * (x2.y / (1.f + expf(-x2.y)));
            *(uint32_t*)(xmf + mr8*2048 + col) = pack2(__float2half_rn(r0), __float2half_rn(r1));
        }
    }
}

// ---------------- host ----------------
extern "C" void kernel_launch(void* const* d_in, const int* in_sizes, int n_in,
                              void* d_out, int out_size){
    const float* x      = (const float*)d_in[0];
    const float* ln_w   = (const float*)d_in[1];
    const float* ln_b   = (const float*)d_in[2];
    const float* w1     = (const float*)d_in[3];
    const float* b1     = (const float*)d_in[4];
    const float* conv_w = (const float*)d_in[5];
    const float* conv_b = (const float*)d_in[6];
    const float* skip   = (const float*)d_in[7];
    const float* wqk    = (const float*)d_in[8];
    const float* bqk    = (const float*)d_in[9];
    const float* wv     = (const float*)d_in[10];
    const float* bv     = (const float*)d_in[11];
    const float* wif    = (const float*)d_in[12];
    const float* bif    = (const float*)d_in[13];
    const float* hn_w   = (const float*)d_in[14];
    const float* w2     = (const float*)d_in[15];
    const float* b2     = (const float*)d_in[16];
    float* out = (float*)d_out;

    fp16 *xlnf,*x1f,*qkf,*xmf,*pjf,*vbf;
    fp16 *w1f,*cwtf,*wqkTf,*wvTf,*w2f;
    float *y,*qkb,*gates,*gA,*MA,*eA;
    cudaGetSymbolAddress((void**)&xlnf, d_xlnf);
    cudaGetSymbolAddress((void**)&y,    d_y);
    cudaGetSymbolAddress((void**)&x1f,  d_x1f);
    cudaGetSymbolAddress((void**)&qkb,  d_qk);
    cudaGetSymbolAddress((void**)&qkf,  d_qkf);
    cudaGetSymbolAddress((void**)&pjf,  d_pjf);
    cudaGetSymbolAddress((void**)&vbf,  d_vbf);
    cudaGetSymbolAddress((void**)&xmf,  d_xmf);
    cudaGetSymbolAddress((void**)&gates,d_gates);
    cudaGetSymbolAddress((void**)&gA,   d_g);
    cudaGetSymbolAddress((void**)&MA,   d_M);
    cudaGetSymbolAddress((void**)&eA,   d_enm);
    cudaGetSymbolAddress((void**)&w1f,  d_w1f);
    cudaGetSymbolAddress((void**)&cwtf, d_cwtf);
    cudaGetSymbolAddress((void**)&wqkTf,d_wqkTf);
    cudaGetSymbolAddress((void**)&wvTf, d_wvTf);
    cudaGetSymbolAddress((void**)&w2f,  d_w2f);

    cudaFuncSetAttribute(hgemm<2>, cudaFuncAttributeMaxDynamicSharedMemorySize, 110592);
    cudaFuncSetAttribute(hgemm<1>, cudaFuncAttributeMaxDynamicSharedMemorySize, 82944);
    cudaFuncSetAttribute(attn2, cudaFuncAttributeMaxDynamicSharedMemorySize, ATT_SMEM);

    // order chosen so ncu's captured slot (4th launch) hits hgemm<2> GEMM1
    quant_plain4<<<(int)((4096L*1024/4 + 255)/256), 256>>>((const float4*)w1, (__half2*)w1f, 4096L*1024/4);  // 1
    ln_kernel<<<Mq, 256>>>(x, ln_w, ln_b, xlnf);                                                             // 2
    quant_plain4<<<(int)((1024L*2048/4 + 255)/256), 256>>>((const float4*)w2, (__half2*)w2f, 1024L*2048/4);  // 3

    // 4: y = LN(x) @ w1^T + b1 : f32 y only for x2 half + fp16 x1
    {
        G5P p = {};
        p.Af = xlnf; p.Bf = w1f;
        p.Cf = y; p.Oh = x1f; p.bias = b1;
        p.K = 1024; p.lda = 1024; p.ldb = 1024; p.ldc = 4096; p.ldo = 2048;
        p.epi = 1; p.ntaps = 1; p.splitNmax = 2048; p.cfMin = 2048;
        hgemm<2><<<dim3(32, 24, 1), 512, 110592>>>(p);
    }

    prep_cwt<<<(int)(((long)Cq*Cq/2 + 255)/256), 256>>>((const float4*)conv_w, (__half2*)cwtf);
    prep_wqkv<<<(Hq*512*256 + Hq*256*256 + 255)/256, 256>>>(wqk, wv, wqkTf, wvTf);

    // qk = silu(conv(x1)) — batch-dependent taps; heavy blocks first
    {
        G5P p = {};
        p.Af = x1f; p.Bf = cwtf;
        p.Cf = qkb; p.Oh = qkf; p.bias = conv_b;
        p.K = Cq; p.lda = Cq; p.ldb = Cq; p.ldc = Cq; p.ldo = Cq;
        p.epi = 1|2|8; p.splitNmax = Cq; p.cfMin = 0;
        p.ntaps  = 1; p.aTap[0]  = 0;              p.bTap[0]  = (long)3*Cq*Cq;
        p.ntaps2 = 2; p.aTap2[0] = 0;              p.bTap2[0] = (long)2*Cq*Cq;
                      p.aTap2[1] = (long)Lq*Cq;    p.bTap2[1] = (long)3*Cq*Cq;
        hgemm<2><<<dim3(16, 24, 1), 512, 110592>>>(p);
    }

    // per-head proj = qk_h @ wqk_h + bqk  (fp16 only)
    {
        G5P p = {};
        p.Af = qkf; p.Bf = wqkTf;
        p.Cf = 0; p.Oh = pjf; p.bias = bqk;
        p.K = 256; p.lda = 2048; p.ldb = 256; p.ldo = 4096;
        p.aZ = 256; p.bZ = (long)512*256; p.biasZ = 512; p.oZ = 512;
        p.epi = 1; p.ntaps = 1; p.splitNmax = 512;
        hgemm<2><<<dim3(4, 24, Hq), 512, 110592>>>(p);
    }
    // per-head v = x1_h @ wv_h + bv  (fp16 only)
    {
        G5P p = {};
        p.Af = x1f; p.Bf = wvTf;
        p.Cf = 0; p.Oh = vbf; p.bias = bv;
        p.K = 256; p.lda = 2048; p.ldb = 256; p.ldo = 2048;
        p.aZ = 256; p.bZ = (long)256*256; p.biasZ = 256; p.oZ = 256;
        p.epi = 1; p.ntaps = 1; p.splitNmax = 256;
        hgemm<2><<<dim3(2, 24, Hq), 512, 110592>>>(p);
    }

    gates_kernel<<<Mq/16, 256>>>(pjf, vbf, wif, bif, gates);
    scan_kernel<<<Bq*Hq, 512>>>(gates, gA, MA, eA);

    attn2<<<dim3(24, 16), 128, ATT_SMEM>>>(pjf, vbf, qkb, y,
                                           gA, MA, eA, skip, hn_w, xmf);

    // out = xm @ w2^T + b2 + x
    {
        G5P p = {};
        p.Af = xmf; p.Bf = w2f;
        p.Cf = out; p.bias = b2; p.add = x;
        p.K = Cq; p.lda = 2048; p.ldb = 2048; p.ldc = 1024; p.ldadd = 1024;
        p.epi = 1|4; p.ntaps = 1; p.splitNmax = 0; p.cfMin = 0;
        hgemm<1><<<dim3(8, 48, 1), 512, 82944>>>(p);
    }
}

// round 12
// speedup vs baseline: 1.7145x; 1.0327x over previous
#include <cuda_runtime.h>
#include <cuda_fp16.h>
#include <math.h>
#include <stdint.h>

#define Bq 2
#define Lq 1536
#define Dq 1024
#define Hq 8
#define Cq 2048
#define DPHq 256
#define Mq (Bq*Lq)   /* 3072 */

typedef __half fp16;

// ---------------- scratch (static device globals; no allocation) ----------------
__device__ __align__(128) fp16  d_xlnf[(size_t)Mq*Dq];
__device__ __align__(128) float d_y[(size_t)Mq*4096];
__device__ __align__(128) fp16  d_x1f[(size_t)Mq*Cq];
__device__ __align__(128) float d_qk[(size_t)Mq*Cq];
__device__ __align__(128) fp16  d_qkf[(size_t)Mq*Cq];
__device__ __align__(128) fp16  d_pjf[(size_t)Mq*4096];
__device__ __align__(128) fp16  d_vbf[(size_t)Mq*Cq];
__device__ __align__(128) fp16  d_xmf[(size_t)Mq*Cq];
__device__ float d_gates[(size_t)Mq*16];
__device__ float d_g[16*Lq];
__device__ float d_M[16*Lq];
__device__ float d_enm[16*Lq];
__device__ __align__(128) fp16  d_w1f[4096*1024];
__device__ __align__(128) fp16  d_cwtf[(size_t)4*Cq*Cq];
__device__ __align__(128) fp16  d_wqkTf[Hq*512*256];
__device__ __align__(128) fp16  d_wvTf[Hq*256*256];
__device__ __align__(128) fp16  d_w2f[1024*2048];

// ---------------- helpers ----------------
__device__ __forceinline__ uint32_t smem_u32(const void* p){
    return (uint32_t)__cvta_generic_to_shared(p);
}
__device__ __forceinline__ void cp16(uint32_t dst, const void* src){
    asm volatile("cp.async.cg.shared.global [%0], [%1], 16;" :: "r"(dst), "l"(src));
}
__device__ __forceinline__ void cp_commit(){ asm volatile("cp.async.commit_group;" ::: "memory"); }
__device__ __forceinline__ void cp_wait0(){ asm volatile("cp.async.wait_group 0;" ::: "memory"); }
__device__ __forceinline__ void cp_wait1(){ asm volatile("cp.async.wait_group 1;" ::: "memory"); }
__device__ __forceinline__ void cp_wait2(){ asm volatile("cp.async.wait_group 2;" ::: "memory"); }

__device__ __forceinline__ void ldsm_x4(uint32_t* r, uint32_t addr){
    asm volatile("ldmatrix.sync.aligned.m8n8.x4.shared.b16 {%0,%1,%2,%3}, [%4];"
                 : "=r"(r[0]), "=r"(r[1]), "=r"(r[2]), "=r"(r[3]) : "r"(addr));
}
__device__ __forceinline__ void ldsm_x4t(uint32_t* r, uint32_t addr){
    asm volatile("ldmatrix.sync.aligned.m8n8.x4.trans.shared.b16 {%0,%1,%2,%3}, [%4];"
                 : "=r"(r[0]), "=r"(r[1]), "=r"(r[2]), "=r"(r[3]) : "r"(addr));
}
__device__ __forceinline__ void mma16816(float* d, const uint32_t* a, const uint32_t* b){
    asm volatile(
        "mma.sync.aligned.m16n8k16.row.col.f32.f16.f16.f32 "
        "{%0,%1,%2,%3}, {%4,%5,%6,%7}, {%8,%9}, {%0,%1,%2,%3};"
        : "+f"(d[0]), "+f"(d[1]), "+f"(d[2]), "+f"(d[3])
        : "r"(a[0]), "r"(a[1]), "r"(a[2]), "r"(a[3]), "r"(b[0]), "r"(b[1]));
}
__device__ __forceinline__ uint32_t pack2(fp16 a, fp16 b){
    uint16_t ua = *(uint16_t*)&a, ub = *(uint16_t*)&b;
    return (uint32_t)ua | ((uint32_t)ub << 16);
}

// ---------------- prep kernels (coalesced) ----------------
__global__ void quant_plain4(const float4* __restrict__ w, __half2* __restrict__ f, long n4){
    long i = (long)blockIdx.x*256 + threadIdx.x;
    if (i >= n4) return;
    float4 v = w[i];
    f[2*i]   = __floats2half2_rn(v.x, v.y);
    f[2*i+1] = __floats2half2_rn(v.z, v.w);
}
__global__ void prep_cwt(const float4* __restrict__ cw, __half2* __restrict__ f2){
    const long NP = (long)Cq*Cq/2;
    long i = (long)blockIdx.x*256 + threadIdx.x;
    if (i >= NP) return;
    float4 a = cw[2*i], b = cw[2*i+1];
    f2[i]        = __floats2half2_rn(a.x, b.x);
    f2[NP + i]   = __floats2half2_rn(a.y, b.y);
    f2[2*NP + i] = __floats2half2_rn(a.z, b.z);
    f2[3*NP + i] = __floats2half2_rn(a.w, b.w);
}
__global__ void prep_wqkv(const float* __restrict__ wqk, const float* __restrict__ wv,
                          fp16* __restrict__ qf, fp16* __restrict__ vf){
    int idx = blockIdx.x*256 + threadIdx.x;
    if (idx < Hq*512*256){
        int hh = idx/(512*256); int r = idx%(512*256); int o = r/256; int i = r%256;
        qf[idx] = __float2half_rn(wqk[hh*131072 + i*512 + o]);
    } else {
        int j = idx - Hq*512*256;
        if (j < Hq*256*256){
            int hh = j/65536; int r = j%65536; int o = r/256; int i = r%256;
            vf[j] = __float2half_rn(wv[hh*65536 + i*256 + o]);
        }
    }
}

// ---------------- LayerNorm on x -> fp16 ----------------
__global__ __launch_bounds__(256) void ln_kernel(const float* __restrict__ x,
        const float* __restrict__ w, const float* __restrict__ bb,
        fp16* __restrict__ of){
    int m = blockIdx.x, t = threadIdx.x;
    __shared__ float s1[256], s2[256];
    float v[4]; float s = 0.f, q = 0.f;
    #pragma unroll
    for (int u=0;u<4;u++){ v[u] = x[(long)m*Dq + t + u*256]; s += v[u]; q += v[u]*v[u]; }
    s1[t] = s; s2[t] = q; __syncthreads();
    for (int off=128; off; off>>=1){
        if (t < off){ s1[t] += s1[t+off]; s2[t] += s2[t+off]; }
        __syncthreads();
    }
    float mu = s1[0]*(1.f/1024.f);
    float var = s2[0]*(1.f/1024.f) - mu*mu;
    float rs = rsqrtf(var + 1e-5f);
    #pragma unroll
    for (int u=0;u<4;u++){
        int c = t + u*256;
        of[(long)m*Dq + c] = __float2half_rn((v[u]-mu)*rs*w[c] + bb[c]);
    }
}

// ---------------- fp16 mma.sync GEMM (512 threads, BK=64): C = A @ B^T ----------------
// epi bits: 1=bias, 2=silu, 4=residual add, 8=conv mode (batch taps + heavy-first y)
struct G5P {
    const fp16 *Af, *Bf;
    float* Cf;
    fp16 *Oh;
    const float* bias; const float* add;
    int K, lda, ldb, ldc, ldo, ldadd, epi, ntaps, ntaps2, splitNmax, cfMin;
    long aZ, bZ, cZ, biasZ, oZ;
    long aTap[2], bTap[2];
    long aTap2[2], bTap2[2];
};

template<int MT>
__global__ __launch_bounds__(512, 1) void hgemm(G5P p){
    constexpr int BM = MT*64;
    constexpr int TA = BM*144;
    constexpr int TB = 128*144;
    constexpr int STG = TA + TB;
    extern __shared__ char sm[];
    int tid = threadIdx.x;
    int warp = tid >> 5, lane = tid & 31;
    int wm = warp >> 2, wn = warp & 3;

    long byy = (p.epi & 8) ? (long)(gridDim.y - 1 - blockIdx.y) : (long)blockIdx.y;
    long m0 = byy*BM;
    int  n0 = blockIdx.x*128;

    long arow; int ntaps; long aT[2], bT[2];
    if (p.epi & 8){
        int batch = (int)(m0 / Lq);
        arow = m0 - (long)batch*Lq;
        if (batch == 0){ ntaps = p.ntaps;  aT[0]=p.aTap[0];  bT[0]=p.bTap[0];  aT[1]=p.aTap[1];  bT[1]=p.bTap[1]; }
        else           { ntaps = p.ntaps2; aT[0]=p.aTap2[0]; bT[0]=p.bTap2[0]; aT[1]=p.aTap2[1]; bT[1]=p.bTap2[1]; }
    } else {
        arow = m0; ntaps = p.ntaps;
        aT[0]=p.aTap[0]; bT[0]=p.bTap[0]; aT[1]=p.aTap[1]; bT[1]=p.bTap[1];
    }

    long aoff = (long)blockIdx.z*p.aZ + arow*p.lda;
    long boff = (long)blockIdx.z*p.bZ + (long)n0*p.ldb;
    int cpt = p.K >> 6;
    int nch = ntaps * cpt;

    uint32_t smb = smem_u32(sm);
    float acc[MT][4][4] = {};

    auto loadChunk = [&](int c){
        int tap = c / cpt;
        int k0  = (c - tap*cpt) << 6;
        uint32_t stg = smb + (c % 3)*STG;
        const fp16* baseA = p.Af + aoff + aT[tap] + k0;
        #pragma unroll
        for (int j = tid; j < BM*8; j += 512){
            int row = j >> 3, ch = j & 7;
            cp16(stg + row*144 + ch*16, baseA + (long)row*p.lda + ch*8);
        }
        const fp16* baseB = p.Bf + boff + bT[tap] + k0;
        #pragma unroll
        for (int j = tid; j < 1024; j += 512){
            int row = j >> 3, ch = j & 7;
            cp16(stg + TA + row*144 + ch*16, baseB + (long)row*p.ldb + ch*8);
        }
    };

    loadChunk(0); cp_commit();
    if (nch > 1){ loadChunk(1); cp_commit(); }

    for (int c=0; c<nch; c++){
        if (c+2 < nch){ loadChunk(c+2); cp_commit(); cp_wait2(); }
        else if (c+1 < nch){ cp_wait1(); }
        else { cp_wait0(); }
        __syncthreads();

        uint32_t stg = smb + (c % 3)*STG;
        uint32_t aB_ = stg, bB = stg + TA;

        int lr = lane & 15, lcs = lane >> 4;
        int gb = lane >> 3, bnr = lane & 7;
        int rowA = wm*(MT*16) + lr;
        int rowB = wn*32 + ((gb >> 1) << 3) + bnr;

        #pragma unroll
        for (int ks=0; ks<4; ks++){
            uint32_t af[MT][4], bf[4][2];
            uint32_t aoffb = (uint32_t)((rowA*9 + ks*2 + lcs) * 16);
            #pragma unroll
            for (int mt=0; mt<MT; mt++)
                ldsm_x4(af[mt], aB_ + aoffb + mt*2304);
            uint32_t boffb = (uint32_t)((rowB*9 + ks*2 + (gb & 1)) * 16);
            uint32_t t4[4];
            #pragma unroll
            for (int np=0; np<2; np++){
                ldsm_x4(t4, bB + boffb + np*2304);
                bf[np*2][0]=t4[0]; bf[np*2][1]=t4[1]; bf[np*2+1][0]=t4[2]; bf[np*2+1][1]=t4[3];
            }
            #pragma unroll
            for (int mt=0; mt<MT; mt++)
                #pragma unroll
                for (int nt=0; nt<4; nt++)
                    mma16816(acc[mt][nt], af[mt], bf[nt]);
        }
        __syncthreads();
    }

    float* eps = (float*)sm;
    #pragma unroll
    for (int mt=0; mt<MT; mt++){
        int r0 = wm*(MT*16) + mt*16 + (lane >> 2);
        #pragma unroll
        for (int nt=0; nt<4; nt++){
            int c0 = wn*32 + nt*8 + (lane & 3)*2;
            eps[r0*132 + c0]       = acc[mt][nt][0];
            eps[r0*132 + c0 + 1]   = acc[mt][nt][1];
            eps[(r0+8)*132 + c0]   = acc[mt][nt][2];
            eps[(r0+8)*132 + c0+1] = acc[mt][nt][3];
        }
    }
    __syncthreads();

    const float* bias = p.bias ? (p.bias + (long)blockIdx.z*p.biasZ) : (const float*)0;
    long czo = (long)blockIdx.z * p.cZ;
    long ozo = (long)blockIdx.z * p.oZ;
    for (int j = tid; j < BM*128; j += 512){
        int rr = j >> 7, cc = j & 127;
        long m = m0 + rr;
        int n = n0 + cc;
        float val = eps[rr*132 + cc];
        if (bias) val += bias[n];
        if (p.epi & 2){ val = val / (1.f + expf(-val)); }
        if (p.epi & 4){ val += p.add[m*p.ldadd + n]; }
        if (p.Cf && n >= p.cfMin) p.Cf[m*p.ldc + czo + n] = val;
        if (n < p.splitNmax)
            p.Oh[m*p.ldo + ozo + n] = __float2half_rn(val);
    }
}

// ---------------- gates (reads fp16 proj/v) ----------------
__global__ __launch_bounds__(256) void gates_kernel(const fp16* __restrict__ pjf,
        const fp16* __restrict__ vbf, const float* __restrict__ wif,
        const float* __restrict__ bif, float* __restrict__ gates){
    __shared__ float As[16*128];
    __shared__ float Ws[128*17];
    int m0 = blockIdx.x*16;
    int tid = threadIdx.x;
    int r = tid >> 4, g = tid & 15;
    float acc = 0.f;
    for (int j0=0; j0<6144; j0+=128){
        __syncthreads();
        for (int e=tid; e<2048; e+=256){
            int jj = e & 127, rr = e >> 7;
            int j = j0 + jj;
            int hh = j/768, t = j - hh*768;
            long m = m0 + rr;
            fp16 v = (t < 512) ? pjf[m*4096 + hh*512 + t]
                               : vbf[m*2048 + hh*256 + (t-512)];
            As[rr*128 + jj] = __half2float(v);
        }
        for (int e=tid; e<2048; e+=256){
            int jj = e & 127, gg = e >> 7;
            Ws[jj*17 + gg] = wif[(long)gg*6144 + j0 + jj];
        }
        __syncthreads();
        #pragma unroll 8
        for (int j=0;j<128;j++) acc += As[r*128 + j]*Ws[j*17 + g];
    }
    gates[(long)(m0+r)*16 + g] = acc + bif[g];
}

// ---------------- per-(b,h) scans ----------------
__global__ __launch_bounds__(512) void scan_kernel(const float* __restrict__ gates,
        float* __restrict__ ga, float* __restrict__ Ma, float* __restrict__ ea){
    int bh = blockIdx.x, b = bh >> 3, h = bh & 7;
    int t = threadIdx.x;
    __shared__ float sd[512];
    long base = (long)b*Lq;
    float ls[3], fc[3];
    #pragma unroll
    for (int u=0;u<3;u++){
        int l = t*3 + u;
        float f = gates[(base + l)*16 + 8 + h];
        ls[u] = (f >= 0.f) ? -log1pf(expf(-f)) : (f - log1pf(expf(f)));
    }
    float tot = ls[0] + ls[1] + ls[2];
    sd[t] = tot;
    __syncthreads();
    for (int off=1; off<512; off<<=1){
        float add = (t >= off) ? sd[t-off] : 0.f;
        __syncthreads();
        sd[t] += add;
        __syncthreads();
    }
    float excl = (t > 0) ? sd[t-1] : 0.f;
    fc[0] = excl + ls[0]; fc[1] = fc[0] + ls[1]; fc[2] = fc[1] + ls[2];
    __syncthreads();
    float gv[3], pm[3];
    #pragma unroll
    for (int u=0;u<3;u++){
        int l = t*3 + u;
        float ig = gates[(base + l)*16 + h];
        gv[u] = expf(ig) - fc[u];
    }
    pm[0] = gv[0]; pm[1] = fmaxf(pm[0], gv[1]); pm[2] = fmaxf(pm[1], gv[2]);
    sd[t] = pm[2];
    __syncthreads();
    for (int off=1; off<512; off<<=1){
        float add = (t >= off) ? sd[t-off] : -3.4e38f;
        __syncthreads();
        sd[t] = fmaxf(sd[t], add);
        __syncthreads();
    }
    float exm = (t > 0) ? sd[t-1] : -3.4e38f;
    #pragma unroll
    for (int u=0;u<3;u++){
        int l = t*3 + u;
        float Ml = fmaxf(exm, pm[u]);
        ga[(long)bh*Lq + l] = gv[u];
        Ma[(long)bh*Lq + l] = Ml;
        ea[(long)bh*Lq + l] = expf(-fc[u] - Ml);
    }
}

// ---------------- tensor-core mLSTM attention: 256 threads, 128 q-rows/CTA ----------------
// smem: Q 128x528B | K0 | K1 | V0 | V1 (each 64x528B) | E[64]
#define Q_OFF  0
#define K0_OFF 67584
#define V0_OFF 135168
#define E_OFF  202752
#define ATT_SMEM 203008

__global__ __launch_bounds__(256, 1) void attn2(
    const fp16* __restrict__ pjf, const fp16* __restrict__ vbf,
    const float* __restrict__ qk, const float* __restrict__ y,
    const float* __restrict__ ga, const float* __restrict__ Ma,
    const float* __restrict__ ea, const float* __restrict__ skip,
    const float* __restrict__ hnw,
    fp16* __restrict__ xmf)
{
    extern __shared__ char sm[];
    const uint32_t smb = smem_u32(sm);
    float* Esm = (float*)(sm + E_OFF);

    int tid = threadIdx.x, w = tid >> 5, lane = tid & 31;
    int bh = blockIdx.y, b = bh >> 3, h = bh & 7;
    int jj = (int)gridDim.x - 1 - (int)blockIdx.x;   // heavy blocks first
    long mbase = (long)b*Lq;
    int o0 = jj*128;
    int ntiles = 2*jj + 2;

    int rowg = w*16 + (lane >> 2);                   // 0..127
    float F0  = expf(-Ma[(long)bh*Lq + o0 + rowg])     * 0.0625f;
    float F8  = expf(-Ma[(long)bh*Lq + o0 + rowg + 8]) * 0.0625f;
    float en0 = ea[(long)bh*Lq + o0 + rowg];
    float en8 = ea[(long)bh*Lq + o0 + rowg + 8];

    // Q tile: 128 rows x 256 dims
    for (int j = tid; j < 4096; j += 256){
        int row = j >> 5, c = j & 31;
        cp16(smb + Q_OFF + row*528 + c*16, pjf + (mbase + o0 + row)*4096 + h*512 + c*8);
    }
    cp_commit();

    auto issueTile = [&](int it){
        long i0 = (long)it*64;
        uint32_t kb = smb + K0_OFF + (it & 1)*33792;
        uint32_t vb2 = smb + V0_OFF + (it & 1)*33792;
        for (int j = tid; j < 2048; j += 256){
            int row = j >> 5, c = j & 31;
            cp16(kb + row*528 + c*16, pjf + (mbase + i0 + row)*4096 + h*512 + 256 + c*8);
        }
        for (int j = tid; j < 2048; j += 256){
            int row = j >> 5, c = j & 31;
            cp16(vb2 + row*528 + c*16, vbf + (mbase + i0 + row)*2048 + h*256 + c*8);
        }
    };
    issueTile(0); cp_commit();
    issueTile(1); cp_commit();

    float accH[32][4];
    #pragma unroll
    for (int g=0; g<32; g++){ accH[g][0]=0.f; accH[g][1]=0.f; accH[g][2]=0.f; accH[g][3]=0.f; }
    uint32_t pk[8][2];
    float rs0 = 0.f, rs1 = 0.f;

    uint32_t qrow = (uint32_t)((w*16 + (lane & 15))*528 + (lane >> 4)*16);
    int gb = lane >> 3;
    uint32_t krow = (uint32_t)(((((gb >> 1) << 3) + (lane & 7)))*528 + (gb & 1)*16);
    uint32_t vrow = (uint32_t)((lane & 15)*528 + (lane >> 4)*16);

    for (int it = 0; it < ntiles; it++){
        cp_wait1();
        if (tid < 64) Esm[tid] = expf(ga[(long)bh*Lq + (long)it*64 + tid]);
        __syncthreads();

        // warp-uniform skip: this warp's rows all above the key tile
        bool active = (it*64 <= o0 + w*16 + 15);
        if (active){
            uint32_t kb = smb + K0_OFF + (it & 1)*33792;
            uint32_t vb2 = smb + V0_OFF + (it & 1)*33792;

            float sacc[8][4];
            #pragma unroll
            for (int g=0; g<8; g++){ sacc[g][0]=0.f; sacc[g][1]=0.f; sacc[g][2]=0.f; sacc[g][3]=0.f; }
            #pragma unroll
            for (int ks=0; ks<16; ks++){
                uint32_t q4[4];
                ldsm_x4(q4, smb + Q_OFF + qrow + ks*32);
                #pragma unroll
                for (int kt=0; kt<4; kt++){
                    uint32_t b4[4];
                    ldsm_x4(b4, kb + krow + kt*(16*528) + ks*32);
                    mma16816(sacc[kt*2],   q4, b4);
                    mma16816(sacc[kt*2+1], q4, b4 + 2);
                }
            }
            bool needmask = (it*64 + 63 > o0 + w*16);
            int qg0 = o0 + rowg, qg8 = qg0 + 8;
            #pragma unroll
            for (int nt=0; nt<8; nt++){
                int cb = nt*8 + (lane & 3)*2;
                int kg = it*64 + cb;
                float e0 = Esm[cb], e1 = Esm[cb+1];
                float w00 = e0*F0, w01 = e1*F0, w10 = e0*F8, w11 = e1*F8;
                if (needmask){
                    if (kg     > qg0) w00 = 0.f;
                    if (kg + 1 > qg0) w01 = 0.f;
                    if (kg     > qg8) w10 = 0.f;
                    if (kg + 1 > qg8) w11 = 0.f;
                }
                float c0 = sacc[nt][0]*w00, c1 = sacc[nt][1]*w01;
                float c2 = sacc[nt][2]*w10, c3 = sacc[nt][3]*w11;
                rs0 += c0 + c1; rs1 += c2 + c3;
                pk[nt][0] = pack2(__float2half_rn(c0), __float2half_rn(c1));
                pk[nt][1] = pack2(__float2half_rn(c2), __float2half_rn(c3));
            }
            #pragma unroll
            for (int kk=0; kk<4; kk++){
                uint32_t aP[4] = { pk[2*kk][0], pk[2*kk][1], pk[2*kk+1][0], pk[2*kk+1][1] };
                #pragma unroll
                for (int dc=0; dc<16; dc++){
                    uint32_t tH[4];
                    ldsm_x4t(tH, vb2 + vrow + kk*(16*528) + dc*32);
                    mma16816(accH[2*dc],   aP, tH);
                    mma16816(accH[2*dc+1], aP, tH + 2);
                }
            }
        }
        __syncthreads();
        if (it + 2 < ntiles) issueTile(it + 2);
        cp_commit();
    }

    rs0 += __shfl_xor_sync(0xffffffffu, rs0, 1);
    rs0 += __shfl_xor_sync(0xffffffffu, rs0, 2);
    rs1 += __shfl_xor_sync(0xffffffffu, rs1, 1);
    rs1 += __shfl_xor_sync(0xffffffffu, rs1, 2);
    float inv0 = 1.f / fmaxf(fabsf(rs0), en0);
    float inv1 = 1.f / fmaxf(fabsf(rs1), en8);

    float s0=0.f, q0=0.f, s1=0.f, q1=0.f;
    #pragma unroll
    for (int g=0; g<32; g++){
        float v0 = accH[g][0]*inv0, v1 = accH[g][1]*inv0;
        float v2 = accH[g][2]*inv1, v3 = accH[g][3]*inv1;
        accH[g][0]=v0; accH[g][1]=v1; accH[g][2]=v2; accH[g][3]=v3;
        s0 += v0 + v1; q0 += v0*v0 + v1*v1;
        s1 += v2 + v3; q1 += v2*v2 + v3*v3;
    }
    s0 += __shfl_xor_sync(0xffffffffu, s0, 1); s0 += __shfl_xor_sync(0xffffffffu, s0, 2);
    q0 += __shfl_xor_sync(0xffffffffu, q0, 1); q0 += __shfl_xor_sync(0xffffffffu, q0, 2);
    s1 += __shfl_xor_sync(0xffffffffu, s1, 1); s1 += __shfl_xor_sync(0xffffffffu, s1, 2);
    q1 += __shfl_xor_sync(0xffffffffu, q1, 1); q1 += __shfl_xor_sync(0xffffffffu, q1, 2);
    float mu0 = s0*(1.f/256.f), var0 = q0*(1.f/256.f) - mu0*mu0, rst0 = rsqrtf(var0 + 1e-5f);
    float mu1 = s1*(1.f/256.f), var1 = q1*(1.f/256.f) - mu1*mu1, rst1 = rsqrtf(var1 + 1e-5f);

    long mr0 = mbase + o0 + rowg;
    long mr8 = mr0 + 8;
    #pragma unroll
    for (int g=0; g<32; g++){
        int d0 = g*8 + (lane & 3)*2;
        int col = h*256 + d0;
        float2 hw = *(const float2*)(hnw + d0);
        float2 sk = *(const float2*)(skip + col);
        {
            float2 q2 = *(const float2*)(qk + mr0*2048 + col);
            float2 x2 = *(const float2*)(y + mr0*4096 + 2048 + col);
            float hv0 = (accH[g][0] - mu0)*rst0*hw.x;
            float hv1 = (accH[g][1] - mu0)*rst0*hw.y;
            float a0 = hv0 + sk.x*q2.x, a1 = hv1 + sk.y*q2.y;
            float r0 = a0 * (x2.x / (1.f + expf(-x2.x)));
            float r1 = a1 * (x2.y / (1.f + expf(-x2.y)));
            *(uint32_t*)(xmf + mr0*2048 + col) = pack2(__float2half_rn(r0), __float2half_rn(r1));
        }
        {
            float2 q2 = *(const float2*)(qk + mr8*2048 + col);
            float2 x2 = *(const float2*)(y + mr8*4096 + 2048 + col);
            float hv0 = (accH[g][2] - mu1)*rst1*hw.x;
            float hv1 = (accH[g][3] - mu1)*rst1*hw.y;
            float a0 = hv0 + sk.x*q2.x, a1 = hv1 + sk.y*q2.y;
            float r0 = a0 * (x2.x / (1.f + expf(-x2.x)));
            float r1 = a1 * (x2.y / (1.f + expf(-x2.y)));
            *(uint32_t*)(xmf + mr8*2048 + col) = pack2(__float2half_rn(r0), __float2half_rn(r1));
        }
    }
}

// ---------------- host ----------------
extern "C" void kernel_launch(void* const* d_in, const int* in_sizes, int n_in,
                              void* d_out, int out_size){
    const float* x      = (const float*)d_in[0];
    const float* ln_w   = (const float*)d_in[1];
    const float* ln_b   = (const float*)d_in[2];
    const float* w1     = (const float*)d_in[3];
    const float* b1     = (const float*)d_in[4];
    const float* conv_w = (const float*)d_in[5];
    const float* conv_b = (const float*)d_in[6];
    const float* skip   = (const float*)d_in[7];
    const float* wqk    = (const float*)d_in[8];
    const float* bqk    = (const float*)d_in[9];
    const float* wv     = (const float*)d_in[10];
    const float* bv     = (const float*)d_in[11];
    const float* wif    = (const float*)d_in[12];
    const float* bif    = (const float*)d_in[13];
    const float* hn_w   = (const float*)d_in[14];
    const float* w2     = (const float*)d_in[15];
    const float* b2     = (const float*)d_in[16];
    float* out = (float*)d_out;

    fp16 *xlnf,*x1f,*qkf,*xmf,*pjf,*vbf;
    fp16 *w1f,*cwtf,*wqkTf,*wvTf,*w2f;
    float *y,*qkb,*gates,*gA,*MA,*eA;
    cudaGetSymbolAddress((void**)&xlnf, d_xlnf);
    cudaGetSymbolAddress((void**)&y,    d_y);
    cudaGetSymbolAddress((void**)&x1f,  d_x1f);
    cudaGetSymbolAddress((void**)&qkb,  d_qk);
    cudaGetSymbolAddress((void**)&qkf,  d_qkf);
    cudaGetSymbolAddress((void**)&pjf,  d_pjf);
    cudaGetSymbolAddress((void**)&vbf,  d_vbf);
    cudaGetSymbolAddress((void**)&xmf,  d_xmf);
    cudaGetSymbolAddress((void**)&gates,d_gates);
    cudaGetSymbolAddress((void**)&gA,   d_g);
    cudaGetSymbolAddress((void**)&MA,   d_M);
    cudaGetSymbolAddress((void**)&eA,   d_enm);
    cudaGetSymbolAddress((void**)&w1f,  d_w1f);
    cudaGetSymbolAddress((void**)&cwtf, d_cwtf);
    cudaGetSymbolAddress((void**)&wqkTf,d_wqkTf);
    cudaGetSymbolAddress((void**)&wvTf, d_wvTf);
    cudaGetSymbolAddress((void**)&w2f,  d_w2f);

    cudaFuncSetAttribute(hgemm<2>, cudaFuncAttributeMaxDynamicSharedMemorySize, 110592);
    cudaFuncSetAttribute(hgemm<1>, cudaFuncAttributeMaxDynamicSharedMemorySize, 82944);
    cudaFuncSetAttribute(attn2, cudaFuncAttributeMaxDynamicSharedMemorySize, ATT_SMEM);

    // order chosen so ncu's captured slot (4th launch) hits hgemm<2> GEMM1
    quant_plain4<<<(int)((4096L*1024/4 + 255)/256), 256>>>((const float4*)w1, (__half2*)w1f, 4096L*1024/4);  // 1
    ln_kernel<<<Mq, 256>>>(x, ln_w, ln_b, xlnf);                                                             // 2
    quant_plain4<<<(int)((1024L*2048/4 + 255)/256), 256>>>((const float4*)w2, (__half2*)w2f, 1024L*2048/4);  // 3

    // 4: y = LN(x) @ w1^T + b1 : f32 y only for x2 half + fp16 x1
    {
        G5P p = {};
        p.Af = xlnf; p.Bf = w1f;
        p.Cf = y; p.Oh = x1f; p.bias = b1;
        p.K = 1024; p.lda = 1024; p.ldb = 1024; p.ldc = 4096; p.ldo = 2048;
        p.epi = 1; p.ntaps = 1; p.splitNmax = 2048; p.cfMin = 2048;
        hgemm<2><<<dim3(32, 24, 1), 512, 110592>>>(p);
    }

    prep_cwt<<<(int)(((long)Cq*Cq/2 + 255)/256), 256>>>((const float4*)conv_w, (__half2*)cwtf);
    prep_wqkv<<<(Hq*512*256 + Hq*256*256 + 255)/256, 256>>>(wqk, wv, wqkTf, wvTf);

    // qk = silu(conv(x1)) — batch-dependent taps; heavy blocks first
    {
        G5P p = {};
        p.Af = x1f; p.Bf = cwtf;
        p.Cf = qkb; p.Oh = qkf; p.bias = conv_b;
        p.K = Cq; p.lda = Cq; p.ldb = Cq; p.ldc = Cq; p.ldo = Cq;
        p.epi = 1|2|8; p.splitNmax = Cq; p.cfMin = 0;
        p.ntaps  = 1; p.aTap[0]  = 0;              p.bTap[0]  = (long)3*Cq*Cq;
        p.ntaps2 = 2; p.aTap2[0] = 0;              p.bTap2[0] = (long)2*Cq*Cq;
                      p.aTap2[1] = (long)Lq*Cq;    p.bTap2[1] = (long)3*Cq*Cq;
        hgemm<2><<<dim3(16, 24, 1), 512, 110592>>>(p);
    }

    // per-head proj = qk_h @ wqk_h + bqk  (fp16 only)
    {
        G5P p = {};
        p.Af = qkf; p.Bf = wqkTf;
        p.Cf = 0; p.Oh = pjf; p.bias = bqk;
        p.K = 256; p.lda = 2048; p.ldb = 256; p.ldo = 4096;
        p.aZ = 256; p.bZ = (long)512*256; p.biasZ = 512; p.oZ = 512;
        p.epi = 1; p.ntaps = 1; p.splitNmax = 512;
        hgemm<2><<<dim3(4, 24, Hq), 512, 110592>>>(p);
    }
    // per-head v = x1_h @ wv_h + bv  (fp16 only)
    {
        G5P p = {};
        p.Af = x1f; p.Bf = wvTf;
        p.Cf = 0; p.Oh = vbf; p.bias = bv;
        p.K = 256; p.lda = 2048; p.ldb = 256; p.ldo = 2048;
        p.aZ = 256; p.bZ = (long)256*256; p.biasZ = 256; p.oZ = 256;
        p.epi = 1; p.ntaps = 1; p.splitNmax = 256;
        hgemm<2><<<dim3(2, 24, Hq), 512, 110592>>>(p);
    }

    gates_kernel<<<Mq/16, 256>>>(pjf, vbf, wif, bif, gates);
    scan_kernel<<<Bq*Hq, 512>>>(gates, gA, MA, eA);

    attn2<<<dim3(12, 16), 256, ATT_SMEM>>>(pjf, vbf, qkb, y,
                                           gA, MA, eA, skip, hn_w, xmf);

    // out = xm @ w2^T + b2 + x
    {
        G5P p = {};
        p.Af = xmf; p.Bf = w2f;
        p.Cf = out; p.bias = b2; p.add = x;
        p.K = Cq; p.lda = 2048; p.ldb = 2048; p.ldc = 1024; p.ldadd = 1024;
        p.epi = 1|4; p.ntaps = 1; p.splitNmax = 0; p.cfMin = 0;
        hgemm<1><<<dim3(8, 48, 1), 512, 82944>>>(p);
    }
}